// round 1
// baseline (speedup 1.0000x reference)
#include <cuda_runtime.h>
#include <cuda_bf16.h>
#include <math.h>

// ---------------- problem constants ----------------
#define BATCH 4
#define SEQ   4096
#define DIM   1024
#define HEADS 16
#define HD    64
#define WIN   128
#define NW    (SEQ / WIN)         // 32
#define MROWS (BATCH * SEQ)       // 16384
#define HIDDEN 2048               // = 2*DIM
#define FF1N  (2 * HIDDEN)        // 4096

// ---------------- scratch (device globals; allocation-free) ----------------
static __device__ float g_ln  [(size_t)MROWS * DIM];
static __device__ float g_q   [(size_t)MROWS * DIM];
static __device__ float g_k   [(size_t)MROWS * DIM];
static __device__ float g_v   [(size_t)MROWS * DIM];
static __device__ float g_attn[(size_t)MROWS * DIM];
static __device__ float g_x1  [(size_t)MROWS * DIM];
static __device__ float g_proj[(size_t)MROWS * FF1N];
static __device__ float g_h   [(size_t)MROWS * HIDDEN];

// ---------------- LayerNorm: one block per row (1024 elems, 256 thr) -------
__global__ void __launch_bounds__(256) ln_kernel(const float* __restrict__ x,
                                                 const float* __restrict__ g,
                                                 const float* __restrict__ b,
                                                 float* __restrict__ out)
{
    const int row = blockIdx.x;
    const int tid = threadIdx.x;
    const float4 v = ((const float4*)(x + (size_t)row * DIM))[tid];
    float s  = v.x + v.y + v.z + v.w;
    float ss = v.x*v.x + v.y*v.y + v.z*v.z + v.w*v.w;
    #pragma unroll
    for (int o = 16; o; o >>= 1) {
        s  += __shfl_xor_sync(0xffffffffu, s,  o);
        ss += __shfl_xor_sync(0xffffffffu, ss, o);
    }
    __shared__ float s1[8], s2[8];
    const int w = tid >> 5, l = tid & 31;
    if (l == 0) { s1[w] = s; s2[w] = ss; }
    __syncthreads();
    if (w == 0) {
        s  = (l < 8) ? s1[l] : 0.f;
        ss = (l < 8) ? s2[l] : 0.f;
        #pragma unroll
        for (int o = 4; o; o >>= 1) {
            s  += __shfl_xor_sync(0xffffffffu, s,  o);
            ss += __shfl_xor_sync(0xffffffffu, ss, o);
        }
        if (l == 0) { s1[0] = s * (1.f / DIM); s2[0] = ss * (1.f / DIM); }
    }
    __syncthreads();
    const float m   = s1[0];
    const float var = s2[0] - m * m;
    const float r   = rsqrtf(var + 1e-5f);
    const float4 gv = ((const float4*)g)[tid];
    const float4 bv = ((const float4*)b)[tid];
    float4 o;
    o.x = (v.x - m) * r * gv.x + bv.x;
    o.y = (v.y - m) * r * gv.y + bv.y;
    o.z = (v.z - m) * r * gv.z + bv.z;
    o.w = (v.w - m) * r * gv.w + bv.w;
    ((float4*)(out + (size_t)row * DIM))[tid] = o;
}

// ---------------- SGEMM 128x128x8, 8x8/thread, double-buffered -------------
// EPI: 0 = C=AB, 1 = C=AB+bias, 2 = C=AB+bias+res
template<int EPI>
__global__ void __launch_bounds__(256) sgemm_kernel(
    const float* __restrict__ A, const float* __restrict__ B,
    float* __restrict__ C, const float* __restrict__ bias,
    const float* __restrict__ res, int M, int N, int K)
{
    __shared__ float As[2][8][128];
    __shared__ float Bs[2][8][128];
    const int tid = threadIdx.x;
    const int bx = blockIdx.x, by = blockIdx.y;

    const int a_r = tid >> 1, a_c = (tid & 1) << 2;   // A tile: 128 rows x 8 k
    const int b_r = tid >> 5, b_c = (tid & 31) << 2;  // B tile: 8 k x 128 cols

    const float* Ag = A + (size_t)(by * 128 + a_r) * K + a_c;
    const float* Bg = B + (size_t)b_r * N + bx * 128 + b_c;

    float4 av = *(const float4*)Ag;
    float4 bv = *(const float4*)Bg;
    As[0][a_c + 0][a_r] = av.x; As[0][a_c + 1][a_r] = av.y;
    As[0][a_c + 2][a_r] = av.z; As[0][a_c + 3][a_r] = av.w;
    *(float4*)&Bs[0][b_r][b_c] = bv;
    __syncthreads();

    const int tr = (tid >> 4) << 2;   // 0..60
    const int tc = (tid & 15) << 2;   // 0..60
    float acc[8][8] = {};
    int buf = 0;

    for (int k0 = 8;; k0 += 8) {
        const bool more = (k0 < K);
        if (more) {
            av = *(const float4*)(Ag + k0);
            bv = *(const float4*)(Bg + (size_t)k0 * N);
        }
        #pragma unroll
        for (int kk = 0; kk < 8; ++kk) {
            float4 a0 = *(float4*)&As[buf][kk][tr];
            float4 a1 = *(float4*)&As[buf][kk][tr + 64];
            float4 b0 = *(float4*)&Bs[buf][kk][tc];
            float4 b1 = *(float4*)&Bs[buf][kk][tc + 64];
            float ar[8] = {a0.x,a0.y,a0.z,a0.w,a1.x,a1.y,a1.z,a1.w};
            float br[8] = {b0.x,b0.y,b0.z,b0.w,b1.x,b1.y,b1.z,b1.w};
            #pragma unroll
            for (int i = 0; i < 8; ++i)
                #pragma unroll
                for (int j = 0; j < 8; ++j)
                    acc[i][j] += ar[i] * br[j];
        }
        if (!more) break;
        buf ^= 1;
        As[buf][a_c + 0][a_r] = av.x; As[buf][a_c + 1][a_r] = av.y;
        As[buf][a_c + 2][a_r] = av.z; As[buf][a_c + 3][a_r] = av.w;
        *(float4*)&Bs[buf][b_r][b_c] = bv;
        __syncthreads();
    }

    // epilogue: 2x2 quads of 4x4
    #pragma unroll
    for (int ih = 0; ih < 2; ++ih) {
        #pragma unroll
        for (int jh = 0; jh < 2; ++jh) {
            const int cb = bx * 128 + tc + jh * 64;
            float4 bvv = make_float4(0.f, 0.f, 0.f, 0.f);
            if (EPI >= 1) bvv = *(const float4*)(bias + cb);
            #pragma unroll
            for (int r = 0; r < 4; ++r) {
                const int row = by * 128 + tr + ih * 64 + r;
                float4 o;
                o.x = acc[ih * 4 + r][jh * 4 + 0];
                o.y = acc[ih * 4 + r][jh * 4 + 1];
                o.z = acc[ih * 4 + r][jh * 4 + 2];
                o.w = acc[ih * 4 + r][jh * 4 + 3];
                if (EPI >= 1) { o.x += bvv.x; o.y += bvv.y; o.z += bvv.z; o.w += bvv.w; }
                if (EPI == 2) {
                    float4 rv = *(const float4*)(res + (size_t)row * N + cb);
                    o.x += rv.x; o.y += rv.y; o.z += rv.z; o.w += rv.w;
                }
                *(float4*)(C + (size_t)row * N + cb) = o;
            }
        }
    }
}

// ---------------- Sliding-window attention: one block per (n, h, b) --------
// smem: qT[64][128] | kT[64][256] (reused as v[256][64]) | P[128][256] | bias[256]
#define SMEM_ATTN ((64*128 + 64*256 + 128*256 + 256) * 4)

__global__ void __launch_bounds__(256) attn_kernel(
    const float* __restrict__ q, const float* __restrict__ k,
    const float* __restrict__ v, const float* __restrict__ rel_bias,
    float* __restrict__ out)
{
    const int n = blockIdx.x;   // window
    const int h = blockIdx.y;   // head
    const int b = blockIdx.z;   // batch
    extern __shared__ float sm[];
    float* qT = sm;                       // [64][128]
    float* kT = sm + 64 * 128;            // [64][256]  (later v[256][64])
    float* P  = sm + 64 * 128 + 64 * 256; // [128][256]
    float* bs = P + 128 * 256;            // [256]
    const int tid = threadIdx.x;

    bs[tid] = rel_bias[h * 256 + tid];

    const long long qbase = ((long long)(b * SEQ + n * WIN)) * DIM + h * HD;
    // q transposed + pre-scaled (1/sqrt(64) = 0.125)
    for (int t = tid; t < 128 * 16; t += 256) {
        const int i = t >> 4, d4 = (t & 15) << 2;
        float4 val = *(const float4*)(q + qbase + (long long)i * DIM + d4);
        qT[(d4 + 0) * 128 + i] = val.x * 0.125f;
        qT[(d4 + 1) * 128 + i] = val.y * 0.125f;
        qT[(d4 + 2) * 128 + i] = val.z * 0.125f;
        qT[(d4 + 3) * 128 + i] = val.w * 0.125f;
    }
    // k transposed; window n covers global rows n*128-128 .. n*128+127
    const long long kbase = ((long long)(b * SEQ + n * WIN - WIN)) * DIM + h * HD;
    for (int t = tid; t < 256 * 16; t += 256) {
        const int j = t >> 4, d4 = (t & 15) << 2;
        float4 val = make_float4(0.f, 0.f, 0.f, 0.f);
        if (!(n == 0 && j < 128))
            val = *(const float4*)(k + kbase + (long long)j * DIM + d4);
        kT[(d4 + 0) * 256 + j] = val.x;
        kT[(d4 + 1) * 256 + j] = val.y;
        kT[(d4 + 2) * 256 + j] = val.z;
        kT[(d4 + 3) * 256 + j] = val.w;
    }
    __syncthreads();

    // logits: per-thread tile 8 rows x 4 cols, 4 row-group iterations
    const int jc  = (tid & 63) << 2;
    const int rgb = tid >> 6;
    for (int it = 0; it < 4; ++it) {
        const int i0 = (it * 4 + rgb) * 8;
        float acc[8][4] = {};
        #pragma unroll 4
        for (int d = 0; d < 64; ++d) {
            float4 a0 = *(float4*)&qT[d * 128 + i0];
            float4 a1 = *(float4*)&qT[d * 128 + i0 + 4];
            float4 kv = *(float4*)&kT[d * 256 + jc];
            float ar[8] = {a0.x,a0.y,a0.z,a0.w,a1.x,a1.y,a1.z,a1.w};
            float kr[4] = {kv.x,kv.y,kv.z,kv.w};
            #pragma unroll
            for (int r = 0; r < 8; ++r)
                #pragma unroll
                for (int c = 0; c < 4; ++c)
                    acc[r][c] += ar[r] * kr[c];
        }
        #pragma unroll
        for (int r = 0; r < 8; ++r) {
            const int i = i0 + r;
            float4 o;
            float* oc = (float*)&o;
            #pragma unroll
            for (int c = 0; c < 4; ++c) {
                const int j = jc + c;
                const int dist = i + WIN - j;
                const bool valid = (dist >= 0) && (n > 0 || j >= WIN);
                oc[c] = valid ? (acc[r][c] + bs[dist]) : -1e9f;
            }
            *(float4*)&P[i * 256 + jc] = o;
        }
    }
    __syncthreads();

    // softmax: one warp per row (8 warps, 16 rows each)
    const int wid = tid >> 5, lane = tid & 31;
    for (int i = wid; i < 128; i += 8) {
        float vals[8];
        float mx = -1e30f;
        #pragma unroll
        for (int t2 = 0; t2 < 8; ++t2) {
            vals[t2] = P[i * 256 + lane + 32 * t2];
            mx = fmaxf(mx, vals[t2]);
        }
        #pragma unroll
        for (int o = 16; o; o >>= 1) mx = fmaxf(mx, __shfl_xor_sync(0xffffffffu, mx, o));
        float sum = 0.f;
        #pragma unroll
        for (int t2 = 0; t2 < 8; ++t2) { vals[t2] = __expf(vals[t2] - mx); sum += vals[t2]; }
        #pragma unroll
        for (int o = 16; o; o >>= 1) sum += __shfl_xor_sync(0xffffffffu, sum, o);
        const float inv = 1.f / sum;
        #pragma unroll
        for (int t2 = 0; t2 < 8; ++t2) P[i * 256 + lane + 32 * t2] = vals[t2] * inv;
    }
    __syncthreads();

    // load v over kT region: vs[256][64]
    float* vs = kT;
    for (int t = tid; t < 256 * 16; t += 256) {
        const int j = t >> 4, d4 = (t & 15) << 2;
        float4 val = make_float4(0.f, 0.f, 0.f, 0.f);
        if (!(n == 0 && j < 128))
            val = *(const float4*)(v + kbase + (long long)j * DIM + d4);
        *(float4*)&vs[j * 64 + d4] = val;
    }
    __syncthreads();

    // PV: per-thread 4 rows x 4 d-cols, 2 iterations
    const int dc  = (tid & 15) << 2;
    const int rg2 = tid >> 4;
    for (int it = 0; it < 2; ++it) {
        const int i0 = (it * 16 + rg2) * 4;
        float acc[4][4] = {};
        #pragma unroll 4
        for (int j = 0; j < 256; ++j) {
            float4 vv = *(float4*)&vs[j * 64 + dc];
            float vr[4] = {vv.x, vv.y, vv.z, vv.w};
            float p0 = P[(i0 + 0) * 256 + j];
            float p1 = P[(i0 + 1) * 256 + j];
            float p2 = P[(i0 + 2) * 256 + j];
            float p3 = P[(i0 + 3) * 256 + j];
            #pragma unroll
            for (int c = 0; c < 4; ++c) {
                acc[0][c] += p0 * vr[c];
                acc[1][c] += p1 * vr[c];
                acc[2][c] += p2 * vr[c];
                acc[3][c] += p3 * vr[c];
            }
        }
        #pragma unroll
        for (int r = 0; r < 4; ++r) {
            float4 o = make_float4(acc[r][0], acc[r][1], acc[r][2], acc[r][3]);
            *(float4*)(out + qbase + (long long)(i0 + r) * DIM + dc) = o;
        }
    }
}

// ---------------- GEGLU: h = val * gelu_exact(gate) ------------------------
__device__ __forceinline__ float gelu_exact(float x) {
    return 0.5f * x * (1.f + erff(x * 0.70710678118654752f));
}

__global__ void __launch_bounds__(256) geglu_kernel(const float* __restrict__ proj,
                                                    float* __restrict__ hout)
{
    const size_t idx = (size_t)blockIdx.x * 256 + threadIdx.x;  // float4 index into hout
    const size_t m  = idx >> 9;          // 512 float4 per hidden row
    const size_t c4 = (idx & 511) << 2;
    const float4 val = *(const float4*)(proj + m * FF1N + c4);
    const float4 gt  = *(const float4*)(proj + m * FF1N + HIDDEN + c4);
    float4 o;
    o.x = val.x * gelu_exact(gt.x);
    o.y = val.y * gelu_exact(gt.y);
    o.z = val.z * gelu_exact(gt.z);
    o.w = val.w * gelu_exact(gt.w);
    ((float4*)hout)[idx] = o;
}

// ---------------- launch ----------------------------------------------------
extern "C" void kernel_launch(void* const* d_in, const int* in_sizes, int n_in,
                              void* d_out, int out_size)
{
    const float* x     = (const float*)d_in[0];
    const float* ln1_g = (const float*)d_in[1];
    const float* ln1_b = (const float*)d_in[2];
    const float* ln2_g = (const float*)d_in[3];
    const float* ln2_b = (const float*)d_in[4];
    const float* wq    = (const float*)d_in[5];
    const float* wk    = (const float*)d_in[6];
    const float* wv    = (const float*)d_in[7];
    const float* wo    = (const float*)d_in[8];
    const float* bo    = (const float*)d_in[9];
    const float* relb  = (const float*)d_in[10];
    const float* wff1  = (const float*)d_in[11];
    const float* bff1  = (const float*)d_in[12];
    const float* wff2  = (const float*)d_in[13];
    const float* bff2  = (const float*)d_in[14];
    float* out = (float*)d_out;

    float *ln, *q, *k, *v, *attn, *x1, *proj, *hb;
    cudaGetSymbolAddress((void**)&ln,   g_ln);
    cudaGetSymbolAddress((void**)&q,    g_q);
    cudaGetSymbolAddress((void**)&k,    g_k);
    cudaGetSymbolAddress((void**)&v,    g_v);
    cudaGetSymbolAddress((void**)&attn, g_attn);
    cudaGetSymbolAddress((void**)&x1,   g_x1);
    cudaGetSymbolAddress((void**)&proj, g_proj);
    cudaGetSymbolAddress((void**)&hb,   g_h);

    cudaFuncSetAttribute(attn_kernel, cudaFuncAttributeMaxDynamicSharedMemorySize, SMEM_ATTN);

    const dim3 g1024(DIM / 128, MROWS / 128);   // (8, 128)
    const dim3 g4096(FF1N / 128, MROWS / 128);  // (32, 128)

    // 1) ln1 = LN(x)
    ln_kernel<<<MROWS, 256>>>(x, ln1_g, ln1_b, ln);
    // 2) q, k, v projections
    sgemm_kernel<0><<<g1024, 256>>>(ln, wq, q, nullptr, nullptr, MROWS, DIM, DIM);
    sgemm_kernel<0><<<g1024, 256>>>(ln, wk, k, nullptr, nullptr, MROWS, DIM, DIM);
    sgemm_kernel<0><<<g1024, 256>>>(ln, wv, v, nullptr, nullptr, MROWS, DIM, DIM);
    // 3) attention
    attn_kernel<<<dim3(NW, HEADS, BATCH), 256, SMEM_ATTN>>>(q, k, v, relb, attn);
    // 4) x1 = attn @ wo + bo + x
    sgemm_kernel<2><<<g1024, 256>>>(attn, wo, x1, bo, x, MROWS, DIM, DIM);
    // 5) ln2 = LN(x1)
    ln_kernel<<<MROWS, 256>>>(x1, ln2_g, ln2_b, ln);
    // 6) proj = ln2 @ w_ff1 + b_ff1
    sgemm_kernel<1><<<g4096, 256>>>(ln, wff1, proj, bff1, nullptr, MROWS, FF1N, DIM);
    // 7) h = val * gelu(gate)
    geglu_kernel<<<(MROWS * HIDDEN / 4) / 256, 256>>>(proj, hb);
    // 8) out = h @ w_ff2 + b_ff2 + x1
    sgemm_kernel<2><<<g1024, 256>>>(hb, wff2, out, bff2, x1, MROWS, DIM, HIDDEN);
}

// round 3
// speedup vs baseline: 2.0957x; 2.0957x over previous
#include <cuda_runtime.h>
#include <cuda_bf16.h>
#include <math.h>
#include <stdint.h>

// ---------------- problem constants ----------------
#define BATCH 4
#define SEQ   4096
#define DIM   1024
#define HEADS 16
#define HD    64
#define WIN   128
#define NW    (SEQ / WIN)         // 32
#define MROWS (BATCH * SEQ)       // 16384
#define HIDDEN 2048               // = 2*DIM
#define FF1N  (2 * HIDDEN)        // 4096

// ---------------- scratch (device globals; allocation-free) ----------------
static __device__ __align__(128) float g_q   [(size_t)MROWS * DIM];
static __device__ __align__(128) float g_k   [(size_t)MROWS * DIM];
static __device__ __align__(128) float g_v   [(size_t)MROWS * DIM];
static __device__ __align__(128) float g_x1  [(size_t)MROWS * DIM];
static __device__ __align__(128) float g_proj[(size_t)MROWS * FF1N];

static __device__ __align__(128) __nv_bfloat16 g_lnh [(size_t)MROWS * DIM];
static __device__ __align__(128) __nv_bfloat16 g_lnl [(size_t)MROWS * DIM];
static __device__ __align__(128) __nv_bfloat16 g_ath [(size_t)MROWS * DIM];
static __device__ __align__(128) __nv_bfloat16 g_atl [(size_t)MROWS * DIM];
static __device__ __align__(128) __nv_bfloat16 g_hh  [(size_t)MROWS * HIDDEN];
static __device__ __align__(128) __nv_bfloat16 g_hl  [(size_t)MROWS * HIDDEN];

// transposed + hi/lo-split weights (bf16, [N][K] K-major)
#define WT_TOTAL (10u * 1024u * 1024u)
static __device__ __align__(128) __nv_bfloat16 g_bth[WT_TOTAL];
static __device__ __align__(128) __nv_bfloat16 g_btl[WT_TOTAL];

// ================= helpers =================
__device__ __forceinline__ uint32_t smem_u32(const void* p) {
    uint32_t a;
    asm("{ .reg .u64 t; cvta.to.shared.u64 t, %1; cvt.u32.u64 %0, t; }" : "=r"(a) : "l"(p));
    return a;
}

#define CP_ASYNC16(dst, src) \
    asm volatile("cp.async.cg.shared.global [%0], [%1], 16;" :: "r"(dst), "l"(src))
#define CP_COMMIT() asm volatile("cp.async.commit_group;" ::: "memory")
#define CP_WAIT1()  asm volatile("cp.async.wait_group 1;" ::: "memory")

#define LDSM_X4(r0, r1, r2, r3, addr) \
    asm volatile("ldmatrix.sync.aligned.m8n8.x4.shared.b16 {%0,%1,%2,%3}, [%4];" \
        : "=r"(r0), "=r"(r1), "=r"(r2), "=r"(r3) : "r"(addr))

#define MMA16816(d, a, b) \
    asm volatile("mma.sync.aligned.m16n8k16.row.col.f32.bf16.bf16.f32 " \
        "{%0,%1,%2,%3}, {%4,%5,%6,%7}, {%8,%9}, {%0,%1,%2,%3};" \
        : "+f"((d)[0]), "+f"((d)[1]), "+f"((d)[2]), "+f"((d)[3]) \
        : "r"((a)[0]), "r"((a)[1]), "r"((a)[2]), "r"((a)[3]), "r"((b)[0]), "r"((b)[1]))

// smem tile: 128 rows x 32 bf16 (64B), XOR swizzle on 16B quarters
__device__ __forceinline__ uint32_t swz(int r, int q) {
    return (uint32_t)(r * 64 + ((q ^ ((r >> 1) & 3)) << 4));
}

__device__ __forceinline__ void split4(float4 v, uint2& h, uint2& l) {
    __nv_bfloat162 h01 = __floats2bfloat162_rn(v.x, v.y);
    __nv_bfloat162 h23 = __floats2bfloat162_rn(v.z, v.w);
    float lx = v.x - __low2float(h01);
    float ly = v.y - __high2float(h01);
    float lz = v.z - __low2float(h23);
    float lw = v.w - __high2float(h23);
    __nv_bfloat162 l01 = __floats2bfloat162_rn(lx, ly);
    __nv_bfloat162 l23 = __floats2bfloat162_rn(lz, lw);
    h.x = *reinterpret_cast<uint32_t*>(&h01);
    h.y = *reinterpret_cast<uint32_t*>(&h23);
    l.x = *reinterpret_cast<uint32_t*>(&l01);
    l.y = *reinterpret_cast<uint32_t*>(&l23);
}

// ---------------- LayerNorm -> bf16 hi/lo ----------------
__global__ void __launch_bounds__(256) ln_kernel(const float* __restrict__ x,
                                                 const float* __restrict__ g,
                                                 const float* __restrict__ b,
                                                 __nv_bfloat16* __restrict__ oh,
                                                 __nv_bfloat16* __restrict__ ol)
{
    const int row = blockIdx.x;
    const int tid = threadIdx.x;
    const float4 v = ((const float4*)(x + (size_t)row * DIM))[tid];
    float s  = v.x + v.y + v.z + v.w;
    float ss = v.x*v.x + v.y*v.y + v.z*v.z + v.w*v.w;
    #pragma unroll
    for (int o = 16; o; o >>= 1) {
        s  += __shfl_xor_sync(0xffffffffu, s,  o);
        ss += __shfl_xor_sync(0xffffffffu, ss, o);
    }
    __shared__ float s1[8], s2[8];
    const int w = tid >> 5, l = tid & 31;
    if (l == 0) { s1[w] = s; s2[w] = ss; }
    __syncthreads();
    if (w == 0) {
        s  = (l < 8) ? s1[l] : 0.f;
        ss = (l < 8) ? s2[l] : 0.f;
        #pragma unroll
        for (int o = 4; o; o >>= 1) {
            s  += __shfl_xor_sync(0xffffffffu, s,  o);
            ss += __shfl_xor_sync(0xffffffffu, ss, o);
        }
        if (l == 0) { s1[0] = s * (1.f / DIM); s2[0] = ss * (1.f / DIM); }
    }
    __syncthreads();
    const float m   = s1[0];
    const float var = s2[0] - m * m;
    const float r   = rsqrtf(var + 1e-5f);
    const float4 gv = ((const float4*)g)[tid];
    const float4 bv = ((const float4*)b)[tid];
    float4 o;
    o.x = (v.x - m) * r * gv.x + bv.x;
    o.y = (v.y - m) * r * gv.y + bv.y;
    o.z = (v.z - m) * r * gv.z + bv.z;
    o.w = (v.w - m) * r * gv.w + bv.w;
    uint2 hh, ll;
    split4(o, hh, ll);
    ((uint2*)(oh + (size_t)row * DIM))[tid] = hh;
    ((uint2*)(ol + (size_t)row * DIM))[tid] = ll;
}

// ---------------- weight transpose + hi/lo split: W[K][N] -> T[N][K] -------
__global__ void __launch_bounds__(256) wsplit_kernel(const float* __restrict__ W,
    __nv_bfloat16* __restrict__ Th, __nv_bfloat16* __restrict__ Tl, int K, int N)
{
    __shared__ float t[32][33];
    const int n0 = blockIdx.x * 32, k0 = blockIdx.y * 32;
    const int tx = threadIdx.x & 31, ty = threadIdx.x >> 5;
    #pragma unroll
    for (int j = 0; j < 4; ++j)
        t[ty + 8*j][tx] = W[(size_t)(k0 + ty + 8*j) * N + n0 + tx];
    __syncthreads();
    #pragma unroll
    for (int j = 0; j < 4; ++j) {
        const float v = t[tx][ty + 8*j];
        const __nv_bfloat16 h = __float2bfloat16(v);
        const __nv_bfloat16 l = __float2bfloat16(v - __bfloat162float(h));
        const size_t o = (size_t)(n0 + ty + 8*j) * K + k0 + tx;
        Th[o] = h;
        Tl[o] = l;
    }
}

// ---------------- HMMA GEMM: C[M,N] = A*B, bf16 3-product split ------------
// A: Ah/Al bf16 [M][K]; B: Bh/Bl bf16 [N][K] (pre-transposed).
// Block 128x128, BK=32, 3-stage cp.async pipeline, 8 warps (4m x 2n).
#define STAGE_BYTES 32768
#define OFF_AH 0
#define OFF_AL 8192
#define OFF_BH 16384
#define OFF_BL 24576
#define SMEM_MMAGEMM (3 * STAGE_BYTES)   // 98304

template<int EPI>   // 0: C=AB, 1: +bias, 2: +bias+res
__global__ void __launch_bounds__(256, 1) mma_gemm(
    const __nv_bfloat16* __restrict__ Ah, const __nv_bfloat16* __restrict__ Al,
    const __nv_bfloat16* __restrict__ Bh, const __nv_bfloat16* __restrict__ Bl,
    float* __restrict__ C, const float* __restrict__ bias,
    const float* __restrict__ res, int M, int N, int K)
{
    extern __shared__ char smem_raw[];
    const uint32_t sb = smem_u32(smem_raw);
    const int tid = threadIdx.x, lane = tid & 31, warp = tid >> 5;
    const int bx = blockIdx.x, by = blockIdx.y;
    const int wm = (warp & 3) << 5;   // warp M offset: 0,32,64,96
    const int wn = (warp >> 2) << 6;  // warp N offset: 0,64

    const __nv_bfloat16* Ahg = Ah + (size_t)(by * 128) * K;
    const __nv_bfloat16* Alg = Al + (size_t)(by * 128) * K;
    const __nv_bfloat16* Bhg = Bh + (size_t)(bx * 128) * K;
    const __nv_bfloat16* Blg = Bl + (size_t)(bx * 128) * K;

    const int CHUNKS = K >> 5;

    // per-thread load geometry: 2 iterations x (r, q)
    const int r0l = tid >> 2,  q0l = tid & 3;          // idx = tid
    const int r1l = (tid + 256) >> 2, q1l = tid & 3;   // idx = tid+256

    #define LOAD_CHUNK(c, s) do { \
        const uint32_t st_ = sb + (s) * STAGE_BYTES; \
        const int kc_ = (c) << 5; \
        { const uint32_t o_ = swz(r0l, q0l); \
          const size_t go_ = (size_t)r0l * K + kc_ + q0l * 8; \
          CP_ASYNC16(st_ + OFF_AH + o_, Ahg + go_); \
          CP_ASYNC16(st_ + OFF_AL + o_, Alg + go_); \
          CP_ASYNC16(st_ + OFF_BH + o_, Bhg + go_); \
          CP_ASYNC16(st_ + OFF_BL + o_, Blg + go_); } \
        { const uint32_t o_ = swz(r1l, q1l); \
          const size_t go_ = (size_t)r1l * K + kc_ + q1l * 8; \
          CP_ASYNC16(st_ + OFF_AH + o_, Ahg + go_); \
          CP_ASYNC16(st_ + OFF_AL + o_, Alg + go_); \
          CP_ASYNC16(st_ + OFF_BH + o_, Bhg + go_); \
          CP_ASYNC16(st_ + OFF_BL + o_, Blg + go_); } \
    } while (0)

    float acc[2][8][4];
    #pragma unroll
    for (int i = 0; i < 2; ++i)
        #pragma unroll
        for (int j = 0; j < 8; ++j)
            #pragma unroll
            for (int t = 0; t < 4; ++t) acc[i][j][t] = 0.f;

    LOAD_CHUNK(0, 0); CP_COMMIT();
    LOAD_CHUNK(1, 1); CP_COMMIT();

    int stage = 0;
    for (int c = 0; c < CHUNKS; ++c) {
        CP_WAIT1();
        __syncthreads();
        if (c + 2 < CHUNKS) {
            const int s2 = (stage + 2 >= 3) ? stage - 1 : stage + 2;
            LOAD_CHUNK(c + 2, s2);
        }
        CP_COMMIT();

        const uint32_t st = sb + stage * STAGE_BYTES;
        #pragma unroll
        for (int ks = 0; ks < 2; ++ks) {
            uint32_t ah[2][4], al[2][4];
            #pragma unroll
            for (int mt = 0; mt < 2; ++mt) {
                const int row = wm + mt * 16 + (lane & 15);
                const int q   = (ks << 1) + (lane >> 4);
                const uint32_t off = swz(row, q);
                LDSM_X4(ah[mt][0], ah[mt][1], ah[mt][2], ah[mt][3], st + OFF_AH + off);
                LDSM_X4(al[mt][0], al[mt][1], al[mt][2], al[mt][3], st + OFF_AL + off);
            }
            uint32_t bh[8][2], bl[8][2];
            #pragma unroll
            for (int np = 0; np < 4; ++np) {
                const int row = wn + np * 16 + (lane & 7) + ((lane >> 4) << 3);
                const int q   = (ks << 1) + ((lane >> 3) & 1);
                const uint32_t off = swz(row, q);
                uint32_t t0, t1, t2, t3;
                LDSM_X4(t0, t1, t2, t3, st + OFF_BH + off);
                bh[2*np][0] = t0; bh[2*np][1] = t1;
                bh[2*np+1][0] = t2; bh[2*np+1][1] = t3;
                LDSM_X4(t0, t1, t2, t3, st + OFF_BL + off);
                bl[2*np][0] = t0; bl[2*np][1] = t1;
                bl[2*np+1][0] = t2; bl[2*np+1][1] = t3;
            }
            #pragma unroll
            for (int mt = 0; mt < 2; ++mt)
                #pragma unroll
                for (int nt = 0; nt < 8; ++nt) {
                    MMA16816(acc[mt][nt], ah[mt], bh[nt]);
                    MMA16816(acc[mt][nt], ah[mt], bl[nt]);
                    MMA16816(acc[mt][nt], al[mt], bh[nt]);
                }
        }
        stage = (stage == 2) ? 0 : stage + 1;
    }

    // epilogue: direct fp32 stores
    #pragma unroll
    for (int mt = 0; mt < 2; ++mt) {
        const int gr = by * 128 + wm + mt * 16 + (lane >> 2);
        #pragma unroll
        for (int nt = 0; nt < 8; ++nt) {
            const int col = bx * 128 + wn + nt * 8 + ((lane & 3) << 1);
            float2 v0 = make_float2(acc[mt][nt][0], acc[mt][nt][1]);
            float2 v1 = make_float2(acc[mt][nt][2], acc[mt][nt][3]);
            if (EPI >= 1) {
                const float2 bb = *(const float2*)(bias + col);
                v0.x += bb.x; v0.y += bb.y; v1.x += bb.x; v1.y += bb.y;
            }
            if (EPI == 2) {
                const float2 r0v = *(const float2*)(res + (size_t)gr * N + col);
                const float2 r1v = *(const float2*)(res + (size_t)(gr + 8) * N + col);
                v0.x += r0v.x; v0.y += r0v.y; v1.x += r1v.x; v1.y += r1v.y;
            }
            *(float2*)(C + (size_t)gr * N + col) = v0;
            *(float2*)(C + (size_t)(gr + 8) * N + col) = v1;
        }
    }
    #undef LOAD_CHUNK
}

// ---------------- Sliding-window attention (fp32) -> bf16 hi/lo out --------
#define SMEM_ATTN ((64*128 + 64*256 + 128*256 + 256) * 4)

__global__ void __launch_bounds__(256) attn_kernel(
    const float* __restrict__ q, const float* __restrict__ k,
    const float* __restrict__ v, const float* __restrict__ rel_bias,
    __nv_bfloat16* __restrict__ outh, __nv_bfloat16* __restrict__ outl)
{
    const int n = blockIdx.x;
    const int h = blockIdx.y;
    const int b = blockIdx.z;
    extern __shared__ float smf[];
    float* qT = smf;
    float* kT = smf + 64 * 128;
    float* P  = smf + 64 * 128 + 64 * 256;
    float* bs = P + 128 * 256;
    const int tid = threadIdx.x;

    bs[tid] = rel_bias[h * 256 + tid];

    const long long qbase = ((long long)(b * SEQ + n * WIN)) * DIM + h * HD;
    for (int t = tid; t < 128 * 16; t += 256) {
        const int i = t >> 4, d4 = (t & 15) << 2;
        float4 val = *(const float4*)(q + qbase + (long long)i * DIM + d4);
        qT[(d4 + 0) * 128 + i] = val.x * 0.125f;
        qT[(d4 + 1) * 128 + i] = val.y * 0.125f;
        qT[(d4 + 2) * 128 + i] = val.z * 0.125f;
        qT[(d4 + 3) * 128 + i] = val.w * 0.125f;
    }
    const long long kbase = ((long long)(b * SEQ + n * WIN - WIN)) * DIM + h * HD;
    for (int t = tid; t < 256 * 16; t += 256) {
        const int j = t >> 4, d4 = (t & 15) << 2;
        float4 val = make_float4(0.f, 0.f, 0.f, 0.f);
        if (!(n == 0 && j < 128))
            val = *(const float4*)(k + kbase + (long long)j * DIM + d4);
        kT[(d4 + 0) * 256 + j] = val.x;
        kT[(d4 + 1) * 256 + j] = val.y;
        kT[(d4 + 2) * 256 + j] = val.z;
        kT[(d4 + 3) * 256 + j] = val.w;
    }
    __syncthreads();

    const int jc  = (tid & 63) << 2;
    const int rgb = tid >> 6;
    for (int it = 0; it < 4; ++it) {
        const int i0 = (it * 4 + rgb) * 8;
        float acc[8][4] = {};
        #pragma unroll 4
        for (int d = 0; d < 64; ++d) {
            float4 a0 = *(float4*)&qT[d * 128 + i0];
            float4 a1 = *(float4*)&qT[d * 128 + i0 + 4];
            float4 kv = *(float4*)&kT[d * 256 + jc];
            float ar[8] = {a0.x,a0.y,a0.z,a0.w,a1.x,a1.y,a1.z,a1.w};
            float kr[4] = {kv.x,kv.y,kv.z,kv.w};
            #pragma unroll
            for (int r = 0; r < 8; ++r)
                #pragma unroll
                for (int cJ = 0; cJ < 4; ++cJ)
                    acc[r][cJ] += ar[r] * kr[cJ];
        }
        #pragma unroll
        for (int r = 0; r < 8; ++r) {
            const int i = i0 + r;
            float4 o;
            float* oc = (float*)&o;
            #pragma unroll
            for (int cJ = 0; cJ < 4; ++cJ) {
                const int j = jc + cJ;
                const int dist = i + WIN - j;
                const bool valid = (dist >= 0) && (n > 0 || j >= WIN);
                oc[cJ] = valid ? (acc[r][cJ] + bs[dist]) : -1e9f;
            }
            *(float4*)&P[i * 256 + jc] = o;
        }
    }
    __syncthreads();

    const int wid = tid >> 5, lane = tid & 31;
    for (int i = wid; i < 128; i += 8) {
        float vals[8];
        float mx = -1e30f;
        #pragma unroll
        for (int t2 = 0; t2 < 8; ++t2) {
            vals[t2] = P[i * 256 + lane + 32 * t2];
            mx = fmaxf(mx, vals[t2]);
        }
        #pragma unroll
        for (int o = 16; o; o >>= 1) mx = fmaxf(mx, __shfl_xor_sync(0xffffffffu, mx, o));
        float sum = 0.f;
        #pragma unroll
        for (int t2 = 0; t2 < 8; ++t2) { vals[t2] = __expf(vals[t2] - mx); sum += vals[t2]; }
        #pragma unroll
        for (int o = 16; o; o >>= 1) sum += __shfl_xor_sync(0xffffffffu, sum, o);
        const float inv = 1.f / sum;
        #pragma unroll
        for (int t2 = 0; t2 < 8; ++t2) P[i * 256 + lane + 32 * t2] = vals[t2] * inv;
    }
    __syncthreads();

    float* vs = kT;
    for (int t = tid; t < 256 * 16; t += 256) {
        const int j = t >> 4, d4 = (t & 15) << 2;
        float4 val = make_float4(0.f, 0.f, 0.f, 0.f);
        if (!(n == 0 && j < 128))
            val = *(const float4*)(v + kbase + (long long)j * DIM + d4);
        *(float4*)&vs[j * 64 + d4] = val;
    }
    __syncthreads();

    const int dc  = (tid & 15) << 2;
    const int rg2 = tid >> 4;
    for (int it = 0; it < 2; ++it) {
        const int i0 = (it * 16 + rg2) * 4;
        float acc[4][4] = {};
        #pragma unroll 4
        for (int j = 0; j < 256; ++j) {
            float4 vv = *(float4*)&vs[j * 64 + dc];
            float vr[4] = {vv.x, vv.y, vv.z, vv.w};
            float p0 = P[(i0 + 0) * 256 + j];
            float p1 = P[(i0 + 1) * 256 + j];
            float p2 = P[(i0 + 2) * 256 + j];
            float p3 = P[(i0 + 3) * 256 + j];
            #pragma unroll
            for (int cc = 0; cc < 4; ++cc) {
                acc[0][cc] += p0 * vr[cc];
                acc[1][cc] += p1 * vr[cc];
                acc[2][cc] += p2 * vr[cc];
                acc[3][cc] += p3 * vr[cc];
            }
        }
        #pragma unroll
        for (int r = 0; r < 4; ++r) {
            float4 o = make_float4(acc[r][0], acc[r][1], acc[r][2], acc[r][3]);
            uint2 hh, ll;
            split4(o, hh, ll);
            *(uint2*)(outh + qbase + (long long)(i0 + r) * DIM + dc) = hh;
            *(uint2*)(outl + qbase + (long long)(i0 + r) * DIM + dc) = ll;
        }
    }
}

// ---------------- GEGLU -> bf16 hi/lo ----------------
__device__ __forceinline__ float gelu_exact(float x) {
    return 0.5f * x * (1.f + erff(x * 0.70710678118654752f));
}

__global__ void __launch_bounds__(256) geglu_kernel(const float* __restrict__ proj,
                                                    __nv_bfloat16* __restrict__ hh,
                                                    __nv_bfloat16* __restrict__ hl)
{
    const size_t idx = (size_t)blockIdx.x * 256 + threadIdx.x;
    const size_t m  = idx >> 9;
    const size_t c4 = (idx & 511) << 2;
    const float4 val = *(const float4*)(proj + m * FF1N + c4);
    const float4 gt  = *(const float4*)(proj + m * FF1N + HIDDEN + c4);
    float4 o;
    o.x = val.x * gelu_exact(gt.x);
    o.y = val.y * gelu_exact(gt.y);
    o.z = val.z * gelu_exact(gt.z);
    o.w = val.w * gelu_exact(gt.w);
    uint2 hhv, llv;
    split4(o, hhv, llv);
    ((uint2*)hh)[idx] = hhv;
    ((uint2*)hl)[idx] = llv;
}

// ---------------- launch ----------------
extern "C" void kernel_launch(void* const* d_in, const int* in_sizes, int n_in,
                              void* d_out, int out_size)
{
    const float* x     = (const float*)d_in[0];
    const float* ln1_g = (const float*)d_in[1];
    const float* ln1_b = (const float*)d_in[2];
    const float* ln2_g = (const float*)d_in[3];
    const float* ln2_b = (const float*)d_in[4];
    const float* wq    = (const float*)d_in[5];
    const float* wk    = (const float*)d_in[6];
    const float* wv    = (const float*)d_in[7];
    const float* wo    = (const float*)d_in[8];
    const float* bo    = (const float*)d_in[9];
    const float* relb  = (const float*)d_in[10];
    const float* wff1  = (const float*)d_in[11];
    const float* bff1  = (const float*)d_in[12];
    const float* wff2  = (const float*)d_in[13];
    const float* bff2  = (const float*)d_in[14];
    float* out = (float*)d_out;

    float *q, *k, *v, *x1, *proj;
    __nv_bfloat16 *lnh, *lnl, *ath, *atl, *hh, *hl, *bth, *btl;
    cudaGetSymbolAddress((void**)&q,    g_q);
    cudaGetSymbolAddress((void**)&k,    g_k);
    cudaGetSymbolAddress((void**)&v,    g_v);
    cudaGetSymbolAddress((void**)&x1,   g_x1);
    cudaGetSymbolAddress((void**)&proj, g_proj);
    cudaGetSymbolAddress((void**)&lnh,  g_lnh);
    cudaGetSymbolAddress((void**)&lnl,  g_lnl);
    cudaGetSymbolAddress((void**)&ath,  g_ath);
    cudaGetSymbolAddress((void**)&atl,  g_atl);
    cudaGetSymbolAddress((void**)&hh,   g_hh);
    cudaGetSymbolAddress((void**)&hl,   g_hl);
    cudaGetSymbolAddress((void**)&bth,  g_bth);
    cudaGetSymbolAddress((void**)&btl,  g_btl);

    cudaFuncSetAttribute(attn_kernel, cudaFuncAttributeMaxDynamicSharedMemorySize, SMEM_ATTN);
    cudaFuncSetAttribute(mma_gemm<0>, cudaFuncAttributeMaxDynamicSharedMemorySize, SMEM_MMAGEMM);
    cudaFuncSetAttribute(mma_gemm<1>, cudaFuncAttributeMaxDynamicSharedMemorySize, SMEM_MMAGEMM);
    cudaFuncSetAttribute(mma_gemm<2>, cudaFuncAttributeMaxDynamicSharedMemorySize, SMEM_MMAGEMM);

    const size_t OW = (size_t)1024 * 1024;
    __nv_bfloat16 *tq_h = bth,        *tq_l = btl;
    __nv_bfloat16 *tk_h = bth + OW,   *tk_l = btl + OW;
    __nv_bfloat16 *tv_h = bth + 2*OW, *tv_l = btl + 2*OW;
    __nv_bfloat16 *to_h = bth + 3*OW, *to_l = btl + 3*OW;
    __nv_bfloat16 *t1_h = bth + 4*OW, *t1_l = btl + 4*OW;   // ff1: 4M elems
    __nv_bfloat16 *t2_h = bth + 8*OW, *t2_l = btl + 8*OW;   // ff2: 2M elems

    wsplit_kernel<<<dim3(32, 32),  256>>>(wq,   tq_h, tq_l, 1024, 1024);
    wsplit_kernel<<<dim3(32, 32),  256>>>(wk,   tk_h, tk_l, 1024, 1024);
    wsplit_kernel<<<dim3(32, 32),  256>>>(wv,   tv_h, tv_l, 1024, 1024);
    wsplit_kernel<<<dim3(32, 32),  256>>>(wo,   to_h, to_l, 1024, 1024);
    wsplit_kernel<<<dim3(128, 32), 256>>>(wff1, t1_h, t1_l, 1024, 4096);
    wsplit_kernel<<<dim3(32, 64),  256>>>(wff2, t2_h, t2_l, 2048, 1024);

    const dim3 g1024(8, 128);
    const dim3 g4096(32, 128);

    ln_kernel<<<MROWS, 256>>>(x, ln1_g, ln1_b, lnh, lnl);
    mma_gemm<0><<<g1024, 256, SMEM_MMAGEMM>>>(lnh, lnl, tq_h, tq_l, q, nullptr, nullptr, MROWS, 1024, 1024);
    mma_gemm<0><<<g1024, 256, SMEM_MMAGEMM>>>(lnh, lnl, tk_h, tk_l, k, nullptr, nullptr, MROWS, 1024, 1024);
    mma_gemm<0><<<g1024, 256, SMEM_MMAGEMM>>>(lnh, lnl, tv_h, tv_l, v, nullptr, nullptr, MROWS, 1024, 1024);
    attn_kernel<<<dim3(NW, HEADS, BATCH), 256, SMEM_ATTN>>>(q, k, v, relb, ath, atl);
    mma_gemm<2><<<g1024, 256, SMEM_MMAGEMM>>>(ath, atl, to_h, to_l, x1, bo, x, MROWS, 1024, 1024);
    ln_kernel<<<MROWS, 256>>>(x1, ln2_g, ln2_b, lnh, lnl);
    mma_gemm<1><<<g4096, 256, SMEM_MMAGEMM>>>(lnh, lnl, t1_h, t1_l, proj, bff1, nullptr, MROWS, 4096, 1024);
    geglu_kernel<<<(MROWS * HIDDEN / 4) / 256, 256>>>(proj, hh, hl);
    mma_gemm<2><<<g1024, 256, SMEM_MMAGEMM>>>(hh, hl, t2_h, t2_l, out, bff2, x1, MROWS, 1024, 2048);
}

// round 4
// speedup vs baseline: 2.1099x; 1.0067x over previous
#include <cuda_runtime.h>
#include <cuda_bf16.h>
#include <math.h>
#include <stdint.h>

// ---------------- problem constants ----------------
#define BATCH 4
#define SEQ   4096
#define DIM   1024
#define HEADS 16
#define HD    64
#define WIN   128
#define NW    (SEQ / WIN)         // 32
#define MROWS (BATCH * SEQ)       // 16384
#define HIDDEN 2048               // = 2*DIM
#define FF1N  (2 * HIDDEN)        // 4096

// ---------------- scratch (device globals; allocation-free) ----------------
static __device__ __align__(128) float g_qkv [(size_t)3 * MROWS * DIM];
static __device__ __align__(128) float g_x1  [(size_t)MROWS * DIM];

static __device__ __align__(128) __nv_bfloat16 g_lnh [(size_t)MROWS * DIM];
static __device__ __align__(128) __nv_bfloat16 g_lnl [(size_t)MROWS * DIM];
static __device__ __align__(128) __nv_bfloat16 g_ath [(size_t)MROWS * DIM];
static __device__ __align__(128) __nv_bfloat16 g_atl [(size_t)MROWS * DIM];
static __device__ __align__(128) __nv_bfloat16 g_hh  [(size_t)MROWS * HIDDEN];
static __device__ __align__(128) __nv_bfloat16 g_hl  [(size_t)MROWS * HIDDEN];

// transposed + hi/lo-split weights (bf16, [N][K] K-major)
// layout: wq @0, wk @1M, wv @2M, wo @3M, ff1(permuted) @4M (4M), ff2 @8M (2M)
#define WT_TOTAL (10u * 1024u * 1024u)
static __device__ __align__(128) __nv_bfloat16 g_bth[WT_TOTAL];
static __device__ __align__(128) __nv_bfloat16 g_btl[WT_TOTAL];

// ================= helpers =================
__device__ __forceinline__ uint32_t smem_u32(const void* p) {
    uint32_t a;
    asm("{ .reg .u64 t; cvta.to.shared.u64 t, %1; cvt.u32.u64 %0, t; }" : "=r"(a) : "l"(p));
    return a;
}

#define CP_ASYNC16(dst, src) \
    asm volatile("cp.async.cg.shared.global [%0], [%1], 16;" :: "r"(dst), "l"(src))
#define CP_COMMIT() asm volatile("cp.async.commit_group;" ::: "memory")
#define CP_WAIT2()  asm volatile("cp.async.wait_group 2;" ::: "memory")

#define LDSM_X4(r0, r1, r2, r3, addr) \
    asm volatile("ldmatrix.sync.aligned.m8n8.x4.shared.b16 {%0,%1,%2,%3}, [%4];" \
        : "=r"(r0), "=r"(r1), "=r"(r2), "=r"(r3) : "r"(addr))

#define MMA16816(d, a, b) \
    asm volatile("mma.sync.aligned.m16n8k16.row.col.f32.bf16.bf16.f32 " \
        "{%0,%1,%2,%3}, {%4,%5,%6,%7}, {%8,%9}, {%0,%1,%2,%3};" \
        : "+f"((d)[0]), "+f"((d)[1]), "+f"((d)[2]), "+f"((d)[3]) \
        : "r"((a)[0]), "r"((a)[1]), "r"((a)[2]), "r"((a)[3]), "r"((b)[0]), "r"((b)[1]))

// smem tile: 128 rows x 32 bf16 (64B/row), XOR swizzle on 16B quarters
__device__ __forceinline__ uint32_t swz(int r, int q) {
    return (uint32_t)(r * 64 + ((q ^ ((r >> 1) & 3)) << 4));
}

__device__ __forceinline__ void split4(float4 v, uint2& h, uint2& l) {
    __nv_bfloat162 h01 = __floats2bfloat162_rn(v.x, v.y);
    __nv_bfloat162 h23 = __floats2bfloat162_rn(v.z, v.w);
    float lx = v.x - __low2float(h01);
    float ly = v.y - __high2float(h01);
    float lz = v.z - __low2float(h23);
    float lw = v.w - __high2float(h23);
    __nv_bfloat162 l01 = __floats2bfloat162_rn(lx, ly);
    __nv_bfloat162 l23 = __floats2bfloat162_rn(lz, lw);
    h.x = *reinterpret_cast<uint32_t*>(&h01);
    h.y = *reinterpret_cast<uint32_t*>(&h23);
    l.x = *reinterpret_cast<uint32_t*>(&l01);
    l.y = *reinterpret_cast<uint32_t*>(&l23);
}

__device__ __forceinline__ float gelu_exact(float x) {
    return 0.5f * x * (1.f + erff(x * 0.70710678118654752f));
}

// ---------------- LayerNorm -> bf16 hi/lo ----------------
__global__ void __launch_bounds__(256) ln_kernel(const float* __restrict__ x,
                                                 const float* __restrict__ g,
                                                 const float* __restrict__ b,
                                                 __nv_bfloat16* __restrict__ oh,
                                                 __nv_bfloat16* __restrict__ ol)
{
    const int row = blockIdx.x;
    const int tid = threadIdx.x;
    const float4 v = ((const float4*)(x + (size_t)row * DIM))[tid];
    float s  = v.x + v.y + v.z + v.w;
    float ss = v.x*v.x + v.y*v.y + v.z*v.z + v.w*v.w;
    #pragma unroll
    for (int o = 16; o; o >>= 1) {
        s  += __shfl_xor_sync(0xffffffffu, s,  o);
        ss += __shfl_xor_sync(0xffffffffu, ss, o);
    }
    __shared__ float s1[8], s2[8];
    const int w = tid >> 5, l = tid & 31;
    if (l == 0) { s1[w] = s; s2[w] = ss; }
    __syncthreads();
    if (w == 0) {
        s  = (l < 8) ? s1[l] : 0.f;
        ss = (l < 8) ? s2[l] : 0.f;
        #pragma unroll
        for (int o = 4; o; o >>= 1) {
            s  += __shfl_xor_sync(0xffffffffu, s,  o);
            ss += __shfl_xor_sync(0xffffffffu, ss, o);
        }
        if (l == 0) { s1[0] = s * (1.f / DIM); s2[0] = ss * (1.f / DIM); }
    }
    __syncthreads();
    const float m   = s1[0];
    const float var = s2[0] - m * m;
    const float r   = rsqrtf(var + 1e-5f);
    const float4 gv = ((const float4*)g)[tid];
    const float4 bv = ((const float4*)b)[tid];
    float4 o;
    o.x = (v.x - m) * r * gv.x + bv.x;
    o.y = (v.y - m) * r * gv.y + bv.y;
    o.z = (v.z - m) * r * gv.z + bv.z;
    o.w = (v.w - m) * r * gv.w + bv.w;
    uint2 hh, ll;
    split4(o, hh, ll);
    ((uint2*)(oh + (size_t)row * DIM))[tid] = hh;
    ((uint2*)(ol + (size_t)row * DIM))[tid] = ll;
}

// ---------------- weight transpose + hi/lo split: W[K][N] -> T[N][K] -------
// PERM=1: geglu column interleave — output row n' sources W column
//         (n'&1) ? (n'>>1)+HIDDEN : (n'>>1)
template<int PERM>
__global__ void __launch_bounds__(256) wsplit_kernel(const float* __restrict__ W,
    __nv_bfloat16* __restrict__ Th, __nv_bfloat16* __restrict__ Tl, int K, int N)
{
    __shared__ float t[32][33];
    const int n0 = blockIdx.x * 32, k0 = blockIdx.y * 32;
    const int tx = threadIdx.x & 31, ty = threadIdx.x >> 5;
    int sc = n0 + tx;
    if (PERM) sc = (sc & 1) ? (sc >> 1) + HIDDEN : (sc >> 1);
    #pragma unroll
    for (int j = 0; j < 4; ++j)
        t[ty + 8*j][tx] = W[(size_t)(k0 + ty + 8*j) * N + sc];
    __syncthreads();
    #pragma unroll
    for (int j = 0; j < 4; ++j) {
        const float v = t[tx][ty + 8*j];
        const __nv_bfloat16 h = __float2bfloat16(v);
        const __nv_bfloat16 l = __float2bfloat16(v - __bfloat162float(h));
        const size_t o = (size_t)(n0 + ty + 8*j) * K + k0 + tx;
        Th[o] = h;
        Tl[o] = l;
    }
}

// ---------------- HMMA GEMM: C[M,N] = A*B, bf16 3-product split ------------
// A: Ah/Al bf16 [M][K]; B: Bh/Bl bf16 [N][K] (pre-transposed).
// Block 128x128, BK=32, 4-stage cp.async pipeline (wait_group 2), 8 warps 4x2.
// EPI: 0 C=AB | 2 C=AB+bias+res | 3 fused geglu -> bf16 hi/lo (N halved)
// QKV: if 1, output column-blocks route to q/k/v slabs (each M x 1024).
#define STAGE_BYTES 32768
#define OFF_AH 0
#define OFF_AL 8192
#define OFF_BH 16384
#define OFF_BL 24576
#define SMEM_MMAGEMM (4 * STAGE_BYTES)   // 131072

template<int EPI, int QKV>
__global__ void __launch_bounds__(256, 1) mma_gemm(
    const __nv_bfloat16* __restrict__ Ah, const __nv_bfloat16* __restrict__ Al,
    const __nv_bfloat16* __restrict__ Bh, const __nv_bfloat16* __restrict__ Bl,
    float* __restrict__ C, const float* __restrict__ bias,
    const float* __restrict__ res,
    __nv_bfloat16* __restrict__ Oh, __nv_bfloat16* __restrict__ Ol,
    int M, int N, int K)
{
    extern __shared__ char smem_raw[];
    const uint32_t sb = smem_u32(smem_raw);
    const int tid = threadIdx.x, lane = tid & 31, warp = tid >> 5;
    const int bxw = blockIdx.x, by = blockIdx.y;
    const int wm = (warp & 3) << 5;   // warp M offset: 0,32,64,96
    const int wn = (warp >> 2) << 6;  // warp N offset: 0,64

    // output column base (within target slab)
    int bx = bxw;
    if (QKV) {
        C += (size_t)(bxw >> 3) * M * N;   // q/k/v slab
        bx = bxw & 7;
    }

    const __nv_bfloat16* Ahg = Ah + (size_t)(by * 128) * K;
    const __nv_bfloat16* Alg = Al + (size_t)(by * 128) * K;
    const __nv_bfloat16* Bhg = Bh + (size_t)(bxw * 128) * K;
    const __nv_bfloat16* Blg = Bl + (size_t)(bxw * 128) * K;

    const int CHUNKS = K >> 5;

    const int r0l = tid >> 2,  q0l = tid & 3;
    const int r1l = (tid + 256) >> 2, q1l = tid & 3;

    #define LOAD_CHUNK(c, s) do { \
        const uint32_t st_ = sb + (s) * STAGE_BYTES; \
        const int kc_ = (c) << 5; \
        { const uint32_t o_ = swz(r0l, q0l); \
          const size_t go_ = (size_t)r0l * K + kc_ + q0l * 8; \
          CP_ASYNC16(st_ + OFF_AH + o_, Ahg + go_); \
          CP_ASYNC16(st_ + OFF_AL + o_, Alg + go_); \
          CP_ASYNC16(st_ + OFF_BH + o_, Bhg + go_); \
          CP_ASYNC16(st_ + OFF_BL + o_, Blg + go_); } \
        { const uint32_t o_ = swz(r1l, q1l); \
          const size_t go_ = (size_t)r1l * K + kc_ + q1l * 8; \
          CP_ASYNC16(st_ + OFF_AH + o_, Ahg + go_); \
          CP_ASYNC16(st_ + OFF_AL + o_, Alg + go_); \
          CP_ASYNC16(st_ + OFF_BH + o_, Bhg + go_); \
          CP_ASYNC16(st_ + OFF_BL + o_, Blg + go_); } \
    } while (0)

    float acc[2][8][4];
    #pragma unroll
    for (int i = 0; i < 2; ++i)
        #pragma unroll
        for (int j = 0; j < 8; ++j)
            #pragma unroll
            for (int t = 0; t < 4; ++t) acc[i][j][t] = 0.f;

    LOAD_CHUNK(0, 0); CP_COMMIT();
    LOAD_CHUNK(1, 1); CP_COMMIT();
    LOAD_CHUNK(2, 2); CP_COMMIT();

    for (int c = 0; c < CHUNKS; ++c) {
        CP_WAIT2();
        __syncthreads();
        if (c + 3 < CHUNKS) LOAD_CHUNK(c + 3, (c + 3) & 3);
        CP_COMMIT();

        const uint32_t st = sb + (c & 3) * STAGE_BYTES;
        #pragma unroll
        for (int ks = 0; ks < 2; ++ks) {
            uint32_t ah[2][4], al[2][4];
            #pragma unroll
            for (int mt = 0; mt < 2; ++mt) {
                const int row = wm + mt * 16 + (lane & 15);
                const int q   = (ks << 1) + (lane >> 4);
                const uint32_t off = swz(row, q);
                LDSM_X4(ah[mt][0], ah[mt][1], ah[mt][2], ah[mt][3], st + OFF_AH + off);
                LDSM_X4(al[mt][0], al[mt][1], al[mt][2], al[mt][3], st + OFF_AL + off);
            }
            uint32_t bh[8][2], bl[8][2];
            #pragma unroll
            for (int np = 0; np < 4; ++np) {
                const int row = wn + np * 16 + (lane & 7) + ((lane >> 4) << 3);
                const int q   = (ks << 1) + ((lane >> 3) & 1);
                const uint32_t off = swz(row, q);
                uint32_t t0, t1, t2, t3;
                LDSM_X4(t0, t1, t2, t3, st + OFF_BH + off);
                bh[2*np][0] = t0; bh[2*np][1] = t1;
                bh[2*np+1][0] = t2; bh[2*np+1][1] = t3;
                LDSM_X4(t0, t1, t2, t3, st + OFF_BL + off);
                bl[2*np][0] = t0; bl[2*np][1] = t1;
                bl[2*np+1][0] = t2; bl[2*np+1][1] = t3;
            }
            #pragma unroll
            for (int mt = 0; mt < 2; ++mt)
                #pragma unroll
                for (int nt = 0; nt < 8; ++nt) {
                    MMA16816(acc[mt][nt], ah[mt], bh[nt]);
                    MMA16816(acc[mt][nt], ah[mt], bl[nt]);
                    MMA16816(acc[mt][nt], al[mt], bh[nt]);
                }
        }
    }

    if (EPI == 3) {
        // fused GEGLU: even col = val_j, odd col = gate_j, j = col>>1
        #pragma unroll
        for (int mt = 0; mt < 2; ++mt) {
            const int gr = by * 128 + wm + mt * 16 + (lane >> 2);
            #pragma unroll
            for (int nt = 0; nt < 8; ++nt) {
                const int col = bx * 128 + wn + nt * 8 + ((lane & 3) << 1);
                const int j = col >> 1;
                const float bv = bias[j];
                const float bg = bias[j + HIDDEN];
                const float h0 = (acc[mt][nt][0] + bv) * gelu_exact(acc[mt][nt][1] + bg);
                const float h1 = (acc[mt][nt][2] + bv) * gelu_exact(acc[mt][nt][3] + bg);
                const __nv_bfloat16 h0h = __float2bfloat16(h0);
                const __nv_bfloat16 h1h = __float2bfloat16(h1);
                Oh[(size_t)gr * HIDDEN + j] = h0h;
                Oh[(size_t)(gr + 8) * HIDDEN + j] = h1h;
                Ol[(size_t)gr * HIDDEN + j] = __float2bfloat16(h0 - __bfloat162float(h0h));
                Ol[(size_t)(gr + 8) * HIDDEN + j] = __float2bfloat16(h1 - __bfloat162float(h1h));
            }
        }
    } else {
        #pragma unroll
        for (int mt = 0; mt < 2; ++mt) {
            const int gr = by * 128 + wm + mt * 16 + (lane >> 2);
            #pragma unroll
            for (int nt = 0; nt < 8; ++nt) {
                const int col = bx * 128 + wn + nt * 8 + ((lane & 3) << 1);
                float2 v0 = make_float2(acc[mt][nt][0], acc[mt][nt][1]);
                float2 v1 = make_float2(acc[mt][nt][2], acc[mt][nt][3]);
                if (EPI >= 1) {
                    const float2 bb = *(const float2*)(bias + col);
                    v0.x += bb.x; v0.y += bb.y; v1.x += bb.x; v1.y += bb.y;
                }
                if (EPI == 2) {
                    const float2 r0v = *(const float2*)(res + (size_t)gr * N + col);
                    const float2 r1v = *(const float2*)(res + (size_t)(gr + 8) * N + col);
                    v0.x += r0v.x; v0.y += r0v.y; v1.x += r1v.x; v1.y += r1v.y;
                }
                *(float2*)(C + (size_t)gr * N + col) = v0;
                *(float2*)(C + (size_t)(gr + 8) * N + col) = v1;
            }
        }
    }
    #undef LOAD_CHUNK
}

// ---------------- Sliding-window attention (fp32) -> bf16 hi/lo out --------
#define SMEM_ATTN ((64*128 + 64*256 + 128*256 + 256) * 4)

__global__ void __launch_bounds__(256) attn_kernel(
    const float* __restrict__ q, const float* __restrict__ k,
    const float* __restrict__ v, const float* __restrict__ rel_bias,
    __nv_bfloat16* __restrict__ outh, __nv_bfloat16* __restrict__ outl)
{
    const int n = blockIdx.x;
    const int h = blockIdx.y;
    const int b = blockIdx.z;
    extern __shared__ float smf[];
    float* qT = smf;
    float* kT = smf + 64 * 128;
    float* P  = smf + 64 * 128 + 64 * 256;
    float* bs = P + 128 * 256;
    const int tid = threadIdx.x;

    bs[tid] = rel_bias[h * 256 + tid];

    const long long qbase = ((long long)(b * SEQ + n * WIN)) * DIM + h * HD;
    for (int t = tid; t < 128 * 16; t += 256) {
        const int i = t >> 4, d4 = (t & 15) << 2;
        float4 val = *(const float4*)(q + qbase + (long long)i * DIM + d4);
        qT[(d4 + 0) * 128 + i] = val.x * 0.125f;
        qT[(d4 + 1) * 128 + i] = val.y * 0.125f;
        qT[(d4 + 2) * 128 + i] = val.z * 0.125f;
        qT[(d4 + 3) * 128 + i] = val.w * 0.125f;
    }
    const long long kbase = ((long long)(b * SEQ + n * WIN - WIN)) * DIM + h * HD;
    for (int t = tid; t < 256 * 16; t += 256) {
        const int j = t >> 4, d4 = (t & 15) << 2;
        float4 val = make_float4(0.f, 0.f, 0.f, 0.f);
        if (!(n == 0 && j < 128))
            val = *(const float4*)(k + kbase + (long long)j * DIM + d4);
        kT[(d4 + 0) * 256 + j] = val.x;
        kT[(d4 + 1) * 256 + j] = val.y;
        kT[(d4 + 2) * 256 + j] = val.z;
        kT[(d4 + 3) * 256 + j] = val.w;
    }
    __syncthreads();

    const int jc  = (tid & 63) << 2;
    const int rgb = tid >> 6;
    for (int it = 0; it < 4; ++it) {
        const int i0 = (it * 4 + rgb) * 8;
        float acc[8][4] = {};
        #pragma unroll 4
        for (int d = 0; d < 64; ++d) {
            float4 a0 = *(float4*)&qT[d * 128 + i0];
            float4 a1 = *(float4*)&qT[d * 128 + i0 + 4];
            float4 kv = *(float4*)&kT[d * 256 + jc];
            float ar[8] = {a0.x,a0.y,a0.z,a0.w,a1.x,a1.y,a1.z,a1.w};
            float kr[4] = {kv.x,kv.y,kv.z,kv.w};
            #pragma unroll
            for (int r = 0; r < 8; ++r)
                #pragma unroll
                for (int cJ = 0; cJ < 4; ++cJ)
                    acc[r][cJ] += ar[r] * kr[cJ];
        }
        #pragma unroll
        for (int r = 0; r < 8; ++r) {
            const int i = i0 + r;
            float4 o;
            float* oc = (float*)&o;
            #pragma unroll
            for (int cJ = 0; cJ < 4; ++cJ) {
                const int j = jc + cJ;
                const int dist = i + WIN - j;
                const bool valid = (dist >= 0) && (n > 0 || j >= WIN);
                oc[cJ] = valid ? (acc[r][cJ] + bs[dist]) : -1e9f;
            }
            *(float4*)&P[i * 256 + jc] = o;
        }
    }
    __syncthreads();

    const int wid = tid >> 5, lane = tid & 31;
    for (int i = wid; i < 128; i += 8) {
        float vals[8];
        float mx = -1e30f;
        #pragma unroll
        for (int t2 = 0; t2 < 8; ++t2) {
            vals[t2] = P[i * 256 + lane + 32 * t2];
            mx = fmaxf(mx, vals[t2]);
        }
        #pragma unroll
        for (int o = 16; o; o >>= 1) mx = fmaxf(mx, __shfl_xor_sync(0xffffffffu, mx, o));
        float sum = 0.f;
        #pragma unroll
        for (int t2 = 0; t2 < 8; ++t2) { vals[t2] = __expf(vals[t2] - mx); sum += vals[t2]; }
        #pragma unroll
        for (int o = 16; o; o >>= 1) sum += __shfl_xor_sync(0xffffffffu, sum, o);
        const float inv = 1.f / sum;
        #pragma unroll
        for (int t2 = 0; t2 < 8; ++t2) P[i * 256 + lane + 32 * t2] = vals[t2] * inv;
    }
    __syncthreads();

    float* vs = kT;
    for (int t = tid; t < 256 * 16; t += 256) {
        const int j = t >> 4, d4 = (t & 15) << 2;
        float4 val = make_float4(0.f, 0.f, 0.f, 0.f);
        if (!(n == 0 && j < 128))
            val = *(const float4*)(v + kbase + (long long)j * DIM + d4);
        *(float4*)&vs[j * 64 + d4] = val;
    }
    __syncthreads();

    const int dc  = (tid & 15) << 2;
    const int rg2 = tid >> 4;
    for (int it = 0; it < 2; ++it) {
        const int i0 = (it * 16 + rg2) * 4;
        float acc[4][4] = {};
        #pragma unroll 4
        for (int j = 0; j < 256; ++j) {
            float4 vv = *(float4*)&vs[j * 64 + dc];
            float vr[4] = {vv.x, vv.y, vv.z, vv.w};
            float p0 = P[(i0 + 0) * 256 + j];
            float p1 = P[(i0 + 1) * 256 + j];
            float p2 = P[(i0 + 2) * 256 + j];
            float p3 = P[(i0 + 3) * 256 + j];
            #pragma unroll
            for (int cc = 0; cc < 4; ++cc) {
                acc[0][cc] += p0 * vr[cc];
                acc[1][cc] += p1 * vr[cc];
                acc[2][cc] += p2 * vr[cc];
                acc[3][cc] += p3 * vr[cc];
            }
        }
        #pragma unroll
        for (int r = 0; r < 4; ++r) {
            float4 o = make_float4(acc[r][0], acc[r][1], acc[r][2], acc[r][3]);
            uint2 hh, ll;
            split4(o, hh, ll);
            *(uint2*)(outh + qbase + (long long)(i0 + r) * DIM + dc) = hh;
            *(uint2*)(outl + qbase + (long long)(i0 + r) * DIM + dc) = ll;
        }
    }
}

// ---------------- launch ----------------
extern "C" void kernel_launch(void* const* d_in, const int* in_sizes, int n_in,
                              void* d_out, int out_size)
{
    const float* x     = (const float*)d_in[0];
    const float* ln1_g = (const float*)d_in[1];
    const float* ln1_b = (const float*)d_in[2];
    const float* ln2_g = (const float*)d_in[3];
    const float* ln2_b = (const float*)d_in[4];
    const float* wq    = (const float*)d_in[5];
    const float* wk    = (const float*)d_in[6];
    const float* wv    = (const float*)d_in[7];
    const float* wo    = (const float*)d_in[8];
    const float* bo    = (const float*)d_in[9];
    const float* relb  = (const float*)d_in[10];
    const float* wff1  = (const float*)d_in[11];
    const float* bff1  = (const float*)d_in[12];
    const float* wff2  = (const float*)d_in[13];
    const float* bff2  = (const float*)d_in[14];
    float* out = (float*)d_out;

    float *qkv, *x1;
    __nv_bfloat16 *lnh, *lnl, *ath, *atl, *hh, *hl, *bth, *btl;
    cudaGetSymbolAddress((void**)&qkv,  g_qkv);
    cudaGetSymbolAddress((void**)&x1,   g_x1);
    cudaGetSymbolAddress((void**)&lnh,  g_lnh);
    cudaGetSymbolAddress((void**)&lnl,  g_lnl);
    cudaGetSymbolAddress((void**)&ath,  g_ath);
    cudaGetSymbolAddress((void**)&atl,  g_atl);
    cudaGetSymbolAddress((void**)&hh,   g_hh);
    cudaGetSymbolAddress((void**)&hl,   g_hl);
    cudaGetSymbolAddress((void**)&bth,  g_bth);
    cudaGetSymbolAddress((void**)&btl,  g_btl);

    float* q = qkv;
    float* k = qkv + (size_t)MROWS * DIM;
    float* v = qkv + (size_t)2 * MROWS * DIM;

    cudaFuncSetAttribute(attn_kernel, cudaFuncAttributeMaxDynamicSharedMemorySize, SMEM_ATTN);
    cudaFuncSetAttribute((mma_gemm<0,1>), cudaFuncAttributeMaxDynamicSharedMemorySize, SMEM_MMAGEMM);
    cudaFuncSetAttribute((mma_gemm<2,0>), cudaFuncAttributeMaxDynamicSharedMemorySize, SMEM_MMAGEMM);
    cudaFuncSetAttribute((mma_gemm<3,0>), cudaFuncAttributeMaxDynamicSharedMemorySize, SMEM_MMAGEMM);

    const size_t OW = (size_t)1024 * 1024;
    __nv_bfloat16 *tq_h = bth,        *tq_l = btl;          // q,k,v stacked
    __nv_bfloat16 *tk_h = bth + OW,   *tk_l = btl + OW;
    __nv_bfloat16 *tv_h = bth + 2*OW, *tv_l = btl + 2*OW;
    __nv_bfloat16 *to_h = bth + 3*OW, *to_l = btl + 3*OW;
    __nv_bfloat16 *t1_h = bth + 4*OW, *t1_l = btl + 4*OW;   // ff1 permuted: 4M
    __nv_bfloat16 *t2_h = bth + 8*OW, *t2_l = btl + 8*OW;   // ff2: 2M

    wsplit_kernel<0><<<dim3(32, 32),  256>>>(wq,   tq_h, tq_l, 1024, 1024);
    wsplit_kernel<0><<<dim3(32, 32),  256>>>(wk,   tk_h, tk_l, 1024, 1024);
    wsplit_kernel<0><<<dim3(32, 32),  256>>>(wv,   tv_h, tv_l, 1024, 1024);
    wsplit_kernel<0><<<dim3(32, 32),  256>>>(wo,   to_h, to_l, 1024, 1024);
    wsplit_kernel<1><<<dim3(128, 32), 256>>>(wff1, t1_h, t1_l, 1024, 4096);
    wsplit_kernel<0><<<dim3(32, 64),  256>>>(wff2, t2_h, t2_l, 2048, 1024);

    const dim3 gqkv(24, 128);
    const dim3 g1024(8, 128);
    const dim3 g4096(32, 128);

    ln_kernel<<<MROWS, 256>>>(x, ln1_g, ln1_b, lnh, lnl);
    mma_gemm<0,1><<<gqkv, 256, SMEM_MMAGEMM>>>(lnh, lnl, tq_h, tq_l, qkv,
        nullptr, nullptr, nullptr, nullptr, MROWS, 1024, 1024);
    attn_kernel<<<dim3(NW, HEADS, BATCH), 256, SMEM_ATTN>>>(q, k, v, relb, ath, atl);
    mma_gemm<2,0><<<g1024, 256, SMEM_MMAGEMM>>>(ath, atl, to_h, to_l, x1,
        bo, x, nullptr, nullptr, MROWS, 1024, 1024);
    ln_kernel<<<MROWS, 256>>>(x1, ln2_g, ln2_b, lnh, lnl);
    mma_gemm<3,0><<<g4096, 256, SMEM_MMAGEMM>>>(lnh, lnl, t1_h, t1_l, nullptr,
        bff1, nullptr, hh, hl, MROWS, 4096, 1024);
    mma_gemm<2,0><<<g1024, 256, SMEM_MMAGEMM>>>(hh, hl, t2_h, t2_l, out,
        bff2, x1, nullptr, nullptr, MROWS, 1024, 2048);
}

// round 5
// speedup vs baseline: 2.7222x; 1.2902x over previous
#include <cuda_runtime.h>
#include <cuda_bf16.h>
#include <cuda_fp16.h>
#include <math.h>
#include <stdint.h>

// ---------------- problem constants ----------------
#define BATCH 4
#define SEQ   4096
#define DIM   1024
#define HEADS 16
#define HD    64
#define WIN   128
#define NW    (SEQ / WIN)         // 32
#define MROWS (BATCH * SEQ)       // 16384
#define HIDDEN 2048               // = 2*DIM
#define FF1N  (2 * HIDDEN)        // 4096

// ---------------- scratch (device globals; allocation-free) ----------------
static __device__ __align__(128) float g_qkv [(size_t)3 * MROWS * DIM];
static __device__ __align__(128) float g_x1  [(size_t)MROWS * DIM];

static __device__ __align__(128) __half g_lnh [(size_t)MROWS * DIM];
static __device__ __align__(128) __half g_lnl [(size_t)MROWS * DIM];
static __device__ __align__(128) __half g_ath [(size_t)MROWS * DIM];
static __device__ __align__(128) __half g_atl [(size_t)MROWS * DIM];
static __device__ __align__(128) __half g_hh  [(size_t)MROWS * HIDDEN];
static __device__ __align__(128) __half g_hl  [(size_t)MROWS * HIDDEN];

// transposed fp16 weights [N][K] K-major
// layout: wq @0, wk @1M, wv @2M, wo @3M, ff1(permuted) @4M (4M), ff2 @8M (2M)
#define WT_TOTAL (10u * 1024u * 1024u)
static __device__ __align__(128) __half g_wt[WT_TOTAL];

// ================= helpers =================
__device__ __forceinline__ uint32_t smem_u32(const void* p) {
    uint32_t a;
    asm("{ .reg .u64 t; cvta.to.shared.u64 t, %1; cvt.u32.u64 %0, t; }" : "=r"(a) : "l"(p));
    return a;
}

#define CP_ASYNC16(dst, src) \
    asm volatile("cp.async.cg.shared.global [%0], [%1], 16;" :: "r"(dst), "l"(src))
#define CP_COMMIT() asm volatile("cp.async.commit_group;" ::: "memory")
#define CP_WAIT2()  asm volatile("cp.async.wait_group 2;" ::: "memory")

#define LDSM_X4(r0, r1, r2, r3, addr) \
    asm volatile("ldmatrix.sync.aligned.m8n8.x4.shared.b16 {%0,%1,%2,%3}, [%4];" \
        : "=r"(r0), "=r"(r1), "=r"(r2), "=r"(r3) : "r"(addr))

#define MMA16816(d, a, b) \
    asm volatile("mma.sync.aligned.m16n8k16.row.col.f32.f16.f16.f32 " \
        "{%0,%1,%2,%3}, {%4,%5,%6,%7}, {%8,%9}, {%0,%1,%2,%3};" \
        : "+f"((d)[0]), "+f"((d)[1]), "+f"((d)[2]), "+f"((d)[3]) \
        : "r"((a)[0]), "r"((a)[1]), "r"((a)[2]), "r"((a)[3]), "r"((b)[0]), "r"((b)[1]))

// smem tile: 128 rows x 32 fp16 (64B/row), XOR swizzle on 16B quarters
__device__ __forceinline__ uint32_t swz(int r, int q) {
    return (uint32_t)(r * 64 + ((q ^ ((r >> 1) & 3)) << 4));
}

// fp32 -> fp16 hi/lo split of 4 values
__device__ __forceinline__ void split4h(float4 v, uint2& h, uint2& l) {
    __half2 h01 = __float22half2_rn(make_float2(v.x, v.y));
    __half2 h23 = __float22half2_rn(make_float2(v.z, v.w));
    float lx = v.x - __low2float(h01);
    float ly = v.y - __high2float(h01);
    float lz = v.z - __low2float(h23);
    float lw = v.w - __high2float(h23);
    __half2 l01 = __float22half2_rn(make_float2(lx, ly));
    __half2 l23 = __float22half2_rn(make_float2(lz, lw));
    h.x = *reinterpret_cast<uint32_t*>(&h01);
    h.y = *reinterpret_cast<uint32_t*>(&h23);
    l.x = *reinterpret_cast<uint32_t*>(&l01);
    l.y = *reinterpret_cast<uint32_t*>(&l23);
}

__device__ __forceinline__ float gelu_exact(float x) {
    return 0.5f * x * (1.f + erff(x * 0.70710678118654752f));
}

// ---------------- LayerNorm -> fp16 hi/lo ----------------
__global__ void __launch_bounds__(256) ln_kernel(const float* __restrict__ x,
                                                 const float* __restrict__ g,
                                                 const float* __restrict__ b,
                                                 __half* __restrict__ oh,
                                                 __half* __restrict__ ol)
{
    const int row = blockIdx.x;
    const int tid = threadIdx.x;
    const float4 v = ((const float4*)(x + (size_t)row * DIM))[tid];
    float s  = v.x + v.y + v.z + v.w;
    float ss = v.x*v.x + v.y*v.y + v.z*v.z + v.w*v.w;
    #pragma unroll
    for (int o = 16; o; o >>= 1) {
        s  += __shfl_xor_sync(0xffffffffu, s,  o);
        ss += __shfl_xor_sync(0xffffffffu, ss, o);
    }
    __shared__ float s1[8], s2[8];
    const int w = tid >> 5, l = tid & 31;
    if (l == 0) { s1[w] = s; s2[w] = ss; }
    __syncthreads();
    if (w == 0) {
        s  = (l < 8) ? s1[l] : 0.f;
        ss = (l < 8) ? s2[l] : 0.f;
        #pragma unroll
        for (int o = 4; o; o >>= 1) {
            s  += __shfl_xor_sync(0xffffffffu, s,  o);
            ss += __shfl_xor_sync(0xffffffffu, ss, o);
        }
        if (l == 0) { s1[0] = s * (1.f / DIM); s2[0] = ss * (1.f / DIM); }
    }
    __syncthreads();
    const float m   = s1[0];
    const float var = s2[0] - m * m;
    const float r   = rsqrtf(var + 1e-5f);
    const float4 gv = ((const float4*)g)[tid];
    const float4 bv = ((const float4*)b)[tid];
    float4 o;
    o.x = (v.x - m) * r * gv.x + bv.x;
    o.y = (v.y - m) * r * gv.y + bv.y;
    o.z = (v.z - m) * r * gv.z + bv.z;
    o.w = (v.w - m) * r * gv.w + bv.w;
    uint2 hh, ll;
    split4h(o, hh, ll);
    ((uint2*)(oh + (size_t)row * DIM))[tid] = hh;
    ((uint2*)(ol + (size_t)row * DIM))[tid] = ll;
}

// ---------------- weight transpose: W[K][N] fp32 -> T[N][K] fp16 -----------
// PERM=1: geglu column interleave — output row n' sources W column
//         (n'&1) ? (n'>>1)+HIDDEN : (n'>>1)
template<int PERM>
__global__ void __launch_bounds__(256) wsplit_kernel(const float* __restrict__ W,
    __half* __restrict__ Th, int K, int N)
{
    __shared__ float t[32][33];
    const int n0 = blockIdx.x * 32, k0 = blockIdx.y * 32;
    const int tx = threadIdx.x & 31, ty = threadIdx.x >> 5;
    int sc = n0 + tx;
    if (PERM) sc = (sc & 1) ? (sc >> 1) + HIDDEN : (sc >> 1);
    #pragma unroll
    for (int j = 0; j < 4; ++j)
        t[ty + 8*j][tx] = W[(size_t)(k0 + ty + 8*j) * N + sc];
    __syncthreads();
    #pragma unroll
    for (int j = 0; j < 4; ++j) {
        const float v = t[tx][ty + 8*j];
        Th[(size_t)(n0 + ty + 8*j) * K + k0 + tx] = __float2half_rn(v);
    }
}

// ---------------- HMMA GEMM: C[M,N] = (Ah+Al)*B, fp16 2-product ------------
// A: Ah/Al fp16 [M][K]; B: fp16 [N][K] (pre-transposed).
// Block 128x128, BK=32, 4-stage cp.async (wait 2), 16 warps (4m x 4n, 32x32).
// EPI: 0 C=AB | 2 C=AB+bias+res | 3 fused geglu -> fp16 hi/lo (cols halved)
// QKV: if 1, output column-blocks route to q/k/v slabs (each M x 1024).
#define STAGE_BYTES 24576
#define OFF_AH 0
#define OFF_AL 8192
#define OFF_B  16384
#define SMEM_MMAGEMM (4 * STAGE_BYTES)   // 98304

template<int EPI, int QKV>
__global__ void __launch_bounds__(512, 1) mma_gemm(
    const __half* __restrict__ Ah, const __half* __restrict__ Al,
    const __half* __restrict__ B,
    float* __restrict__ C, const float* __restrict__ bias,
    const float* __restrict__ res,
    __half* __restrict__ Oh, __half* __restrict__ Ol,
    int M, int N, int K)
{
    extern __shared__ char smem_raw[];
    const uint32_t sb = smem_u32(smem_raw);
    const int tid = threadIdx.x, lane = tid & 31, warp = tid >> 5;
    const int bxw = blockIdx.x, by = blockIdx.y;
    const int wm = (warp & 3) << 5;   // warp M offset: 0,32,64,96
    const int wn = (warp >> 2) << 5;  // warp N offset: 0,32,64,96

    int bx = bxw;
    if (QKV) {
        C += (size_t)(bxw >> 3) * M * N;   // q/k/v slab
        bx = bxw & 7;
    }

    const __half* Ahg = Ah + (size_t)(by * 128) * K;
    const __half* Alg = Al + (size_t)(by * 128) * K;
    const __half* Bg  = B  + (size_t)(bxw * 128) * K;

    const int CHUNKS = K >> 5;

    const int rl = tid >> 2, ql = tid & 3;   // 512 threads = 128 rows x 4 quarters

    #define LOAD_CHUNK(c, s) do { \
        const uint32_t st_ = sb + (s) * STAGE_BYTES; \
        const uint32_t o_ = swz(rl, ql); \
        const size_t go_ = (size_t)rl * K + ((c) << 5) + ql * 8; \
        CP_ASYNC16(st_ + OFF_AH + o_, Ahg + go_); \
        CP_ASYNC16(st_ + OFF_AL + o_, Alg + go_); \
        CP_ASYNC16(st_ + OFF_B  + o_, Bg  + go_); \
    } while (0)

    float acc[2][4][4];
    #pragma unroll
    for (int i = 0; i < 2; ++i)
        #pragma unroll
        for (int j = 0; j < 4; ++j)
            #pragma unroll
            for (int t = 0; t < 4; ++t) acc[i][j][t] = 0.f;

    LOAD_CHUNK(0, 0); CP_COMMIT();
    LOAD_CHUNK(1, 1); CP_COMMIT();
    LOAD_CHUNK(2, 2); CP_COMMIT();

    for (int c = 0; c < CHUNKS; ++c) {
        CP_WAIT2();
        __syncthreads();
        if (c + 3 < CHUNKS) LOAD_CHUNK(c + 3, (c + 3) & 3);
        CP_COMMIT();

        const uint32_t st = sb + (c & 3) * STAGE_BYTES;
        #pragma unroll
        for (int ks = 0; ks < 2; ++ks) {
            uint32_t ah[2][4], al[2][4];
            #pragma unroll
            for (int mt = 0; mt < 2; ++mt) {
                const int row = wm + mt * 16 + (lane & 15);
                const int q   = (ks << 1) + (lane >> 4);
                const uint32_t off = swz(row, q);
                LDSM_X4(ah[mt][0], ah[mt][1], ah[mt][2], ah[mt][3], st + OFF_AH + off);
                LDSM_X4(al[mt][0], al[mt][1], al[mt][2], al[mt][3], st + OFF_AL + off);
            }
            uint32_t bf[4][2];
            #pragma unroll
            for (int np = 0; np < 2; ++np) {
                const int row = wn + np * 16 + (lane & 7) + ((lane >> 4) << 3);
                const int q   = (ks << 1) + ((lane >> 3) & 1);
                const uint32_t off = swz(row, q);
                uint32_t t0, t1, t2, t3;
                LDSM_X4(t0, t1, t2, t3, st + OFF_B + off);
                bf[2*np][0] = t0;   bf[2*np][1] = t1;
                bf[2*np+1][0] = t2; bf[2*np+1][1] = t3;
            }
            #pragma unroll
            for (int mt = 0; mt < 2; ++mt)
                #pragma unroll
                for (int nt = 0; nt < 4; ++nt) {
                    MMA16816(acc[mt][nt], ah[mt], bf[nt]);
                    MMA16816(acc[mt][nt], al[mt], bf[nt]);
                }
        }
    }

    if (EPI == 3) {
        // fused GEGLU: even col = val_j, odd col = gate_j, j = col>>1
        #pragma unroll
        for (int mt = 0; mt < 2; ++mt) {
            const int gr = by * 128 + wm + mt * 16 + (lane >> 2);
            #pragma unroll
            for (int nt = 0; nt < 4; ++nt) {
                const int col = bx * 128 + wn + nt * 8 + ((lane & 3) << 1);
                const int j = col >> 1;
                const float bv = bias[j];
                const float bg = bias[j + HIDDEN];
                const float h0 = (acc[mt][nt][0] + bv) * gelu_exact(acc[mt][nt][1] + bg);
                const float h1 = (acc[mt][nt][2] + bv) * gelu_exact(acc[mt][nt][3] + bg);
                const __half h0h = __float2half_rn(h0);
                const __half h1h = __float2half_rn(h1);
                Oh[(size_t)gr * HIDDEN + j] = h0h;
                Oh[(size_t)(gr + 8) * HIDDEN + j] = h1h;
                Ol[(size_t)gr * HIDDEN + j] = __float2half_rn(h0 - __half2float(h0h));
                Ol[(size_t)(gr + 8) * HIDDEN + j] = __float2half_rn(h1 - __half2float(h1h));
            }
        }
    } else {
        #pragma unroll
        for (int mt = 0; mt < 2; ++mt) {
            const int gr = by * 128 + wm + mt * 16 + (lane >> 2);
            #pragma unroll
            for (int nt = 0; nt < 4; ++nt) {
                const int col = bx * 128 + wn + nt * 8 + ((lane & 3) << 1);
                float2 v0 = make_float2(acc[mt][nt][0], acc[mt][nt][1]);
                float2 v1 = make_float2(acc[mt][nt][2], acc[mt][nt][3]);
                if (EPI >= 1) {
                    const float2 bb = *(const float2*)(bias + col);
                    v0.x += bb.x; v0.y += bb.y; v1.x += bb.x; v1.y += bb.y;
                }
                if (EPI == 2) {
                    const float2 r0v = *(const float2*)(res + (size_t)gr * N + col);
                    const float2 r1v = *(const float2*)(res + (size_t)(gr + 8) * N + col);
                    v0.x += r0v.x; v0.y += r0v.y; v1.x += r1v.x; v1.y += r1v.y;
                }
                *(float2*)(C + (size_t)gr * N + col) = v0;
                *(float2*)(C + (size_t)(gr + 8) * N + col) = v1;
            }
        }
    }
    #undef LOAD_CHUNK
}

// ---------------- Sliding-window attention (fp32) -> fp16 hi/lo out --------
#define SMEM_ATTN ((64*128 + 64*256 + 128*256 + 256) * 4)

__global__ void __launch_bounds__(256) attn_kernel(
    const float* __restrict__ q, const float* __restrict__ k,
    const float* __restrict__ v, const float* __restrict__ rel_bias,
    __half* __restrict__ outh, __half* __restrict__ outl)
{
    const int n = blockIdx.x;
    const int h = blockIdx.y;
    const int b = blockIdx.z;
    extern __shared__ float smf[];
    float* qT = smf;
    float* kT = smf + 64 * 128;
    float* P  = smf + 64 * 128 + 64 * 256;
    float* bs = P + 128 * 256;
    const int tid = threadIdx.x;

    bs[tid] = rel_bias[h * 256 + tid];

    const long long qbase = ((long long)(b * SEQ + n * WIN)) * DIM + h * HD;
    for (int t = tid; t < 128 * 16; t += 256) {
        const int i = t >> 4, d4 = (t & 15) << 2;
        float4 val = *(const float4*)(q + qbase + (long long)i * DIM + d4);
        qT[(d4 + 0) * 128 + i] = val.x * 0.125f;
        qT[(d4 + 1) * 128 + i] = val.y * 0.125f;
        qT[(d4 + 2) * 128 + i] = val.z * 0.125f;
        qT[(d4 + 3) * 128 + i] = val.w * 0.125f;
    }
    const long long kbase = ((long long)(b * SEQ + n * WIN - WIN)) * DIM + h * HD;
    for (int t = tid; t < 256 * 16; t += 256) {
        const int j = t >> 4, d4 = (t & 15) << 2;
        float4 val = make_float4(0.f, 0.f, 0.f, 0.f);
        if (!(n == 0 && j < 128))
            val = *(const float4*)(k + kbase + (long long)j * DIM + d4);
        kT[(d4 + 0) * 256 + j] = val.x;
        kT[(d4 + 1) * 256 + j] = val.y;
        kT[(d4 + 2) * 256 + j] = val.z;
        kT[(d4 + 3) * 256 + j] = val.w;
    }
    __syncthreads();

    const int jc  = (tid & 63) << 2;
    const int rgb = tid >> 6;
    for (int it = 0; it < 4; ++it) {
        const int i0 = (it * 4 + rgb) * 8;
        float acc[8][4] = {};
        #pragma unroll 4
        for (int d = 0; d < 64; ++d) {
            float4 a0 = *(float4*)&qT[d * 128 + i0];
            float4 a1 = *(float4*)&qT[d * 128 + i0 + 4];
            float4 kv = *(float4*)&kT[d * 256 + jc];
            float ar[8] = {a0.x,a0.y,a0.z,a0.w,a1.x,a1.y,a1.z,a1.w};
            float kr[4] = {kv.x,kv.y,kv.z,kv.w};
            #pragma unroll
            for (int r = 0; r < 8; ++r)
                #pragma unroll
                for (int cJ = 0; cJ < 4; ++cJ)
                    acc[r][cJ] += ar[r] * kr[cJ];
        }
        #pragma unroll
        for (int r = 0; r < 8; ++r) {
            const int i = i0 + r;
            float4 o;
            float* oc = (float*)&o;
            #pragma unroll
            for (int cJ = 0; cJ < 4; ++cJ) {
                const int j = jc + cJ;
                const int dist = i + WIN - j;
                const bool valid = (dist >= 0) && (n > 0 || j >= WIN);
                oc[cJ] = valid ? (acc[r][cJ] + bs[dist]) : -1e9f;
            }
            *(float4*)&P[i * 256 + jc] = o;
        }
    }
    __syncthreads();

    const int wid = tid >> 5, lane = tid & 31;
    for (int i = wid; i < 128; i += 8) {
        float vals[8];
        float mx = -1e30f;
        #pragma unroll
        for (int t2 = 0; t2 < 8; ++t2) {
            vals[t2] = P[i * 256 + lane + 32 * t2];
            mx = fmaxf(mx, vals[t2]);
        }
        #pragma unroll
        for (int o = 16; o; o >>= 1) mx = fmaxf(mx, __shfl_xor_sync(0xffffffffu, mx, o));
        float sum = 0.f;
        #pragma unroll
        for (int t2 = 0; t2 < 8; ++t2) { vals[t2] = __expf(vals[t2] - mx); sum += vals[t2]; }
        #pragma unroll
        for (int o = 16; o; o >>= 1) sum += __shfl_xor_sync(0xffffffffu, sum, o);
        const float inv = 1.f / sum;
        #pragma unroll
        for (int t2 = 0; t2 < 8; ++t2) P[i * 256 + lane + 32 * t2] = vals[t2] * inv;
    }
    __syncthreads();

    float* vs = kT;
    for (int t = tid; t < 256 * 16; t += 256) {
        const int j = t >> 4, d4 = (t & 15) << 2;
        float4 val = make_float4(0.f, 0.f, 0.f, 0.f);
        if (!(n == 0 && j < 128))
            val = *(const float4*)(v + kbase + (long long)j * DIM + d4);
        *(float4*)&vs[j * 64 + d4] = val;
    }
    __syncthreads();

    const int dc  = (tid & 15) << 2;
    const int rg2 = tid >> 4;
    for (int it = 0; it < 2; ++it) {
        const int i0 = (it * 16 + rg2) * 4;
        float acc[4][4] = {};
        #pragma unroll 4
        for (int j = 0; j < 256; ++j) {
            float4 vv = *(float4*)&vs[j * 64 + dc];
            float vr[4] = {vv.x, vv.y, vv.z, vv.w};
            float p0 = P[(i0 + 0) * 256 + j];
            float p1 = P[(i0 + 1) * 256 + j];
            float p2 = P[(i0 + 2) * 256 + j];
            float p3 = P[(i0 + 3) * 256 + j];
            #pragma unroll
            for (int cc = 0; cc < 4; ++cc) {
                acc[0][cc] += p0 * vr[cc];
                acc[1][cc] += p1 * vr[cc];
                acc[2][cc] += p2 * vr[cc];
                acc[3][cc] += p3 * vr[cc];
            }
        }
        #pragma unroll
        for (int r = 0; r < 4; ++r) {
            float4 o = make_float4(acc[r][0], acc[r][1], acc[r][2], acc[r][3]);
            uint2 hh, ll;
            split4h(o, hh, ll);
            *(uint2*)(outh + qbase + (long long)(i0 + r) * DIM + dc) = hh;
            *(uint2*)(outl + qbase + (long long)(i0 + r) * DIM + dc) = ll;
        }
    }
}

// ---------------- launch ----------------
extern "C" void kernel_launch(void* const* d_in, const int* in_sizes, int n_in,
                              void* d_out, int out_size)
{
    const float* x     = (const float*)d_in[0];
    const float* ln1_g = (const float*)d_in[1];
    const float* ln1_b = (const float*)d_in[2];
    const float* ln2_g = (const float*)d_in[3];
    const float* ln2_b = (const float*)d_in[4];
    const float* wq    = (const float*)d_in[5];
    const float* wk    = (const float*)d_in[6];
    const float* wv    = (const float*)d_in[7];
    const float* wo    = (const float*)d_in[8];
    const float* bo    = (const float*)d_in[9];
    const float* relb  = (const float*)d_in[10];
    const float* wff1  = (const float*)d_in[11];
    const float* bff1  = (const float*)d_in[12];
    const float* wff2  = (const float*)d_in[13];
    const float* bff2  = (const float*)d_in[14];
    float* out = (float*)d_out;

    float *qkv, *x1;
    __half *lnh, *lnl, *ath, *atl, *hh, *hl, *wt;
    cudaGetSymbolAddress((void**)&qkv,  g_qkv);
    cudaGetSymbolAddress((void**)&x1,   g_x1);
    cudaGetSymbolAddress((void**)&lnh,  g_lnh);
    cudaGetSymbolAddress((void**)&lnl,  g_lnl);
    cudaGetSymbolAddress((void**)&ath,  g_ath);
    cudaGetSymbolAddress((void**)&atl,  g_atl);
    cudaGetSymbolAddress((void**)&hh,   g_hh);
    cudaGetSymbolAddress((void**)&hl,   g_hl);
    cudaGetSymbolAddress((void**)&wt,   g_wt);

    float* q = qkv;
    float* k = qkv + (size_t)MROWS * DIM;
    float* v = qkv + (size_t)2 * MROWS * DIM;

    cudaFuncSetAttribute(attn_kernel, cudaFuncAttributeMaxDynamicSharedMemorySize, SMEM_ATTN);
    cudaFuncSetAttribute((mma_gemm<0,1>), cudaFuncAttributeMaxDynamicSharedMemorySize, SMEM_MMAGEMM);
    cudaFuncSetAttribute((mma_gemm<2,0>), cudaFuncAttributeMaxDynamicSharedMemorySize, SMEM_MMAGEMM);
    cudaFuncSetAttribute((mma_gemm<3,0>), cudaFuncAttributeMaxDynamicSharedMemorySize, SMEM_MMAGEMM);

    const size_t OW = (size_t)1024 * 1024;
    __half *tq = wt;           // q,k,v stacked
    __half *tk = wt + OW;
    __half *tv = wt + 2*OW;
    __half *to = wt + 3*OW;
    __half *t1 = wt + 4*OW;    // ff1 permuted: 4M elems
    __half *t2 = wt + 8*OW;    // ff2: 2M elems

    wsplit_kernel<0><<<dim3(32, 32),  256>>>(wq,   tq, 1024, 1024);
    wsplit_kernel<0><<<dim3(32, 32),  256>>>(wk,   tk, 1024, 1024);
    wsplit_kernel<0><<<dim3(32, 32),  256>>>(wv,   tv, 1024, 1024);
    wsplit_kernel<0><<<dim3(32, 32),  256>>>(wo,   to, 1024, 1024);
    wsplit_kernel<1><<<dim3(128, 32), 256>>>(wff1, t1, 1024, 4096);
    wsplit_kernel<0><<<dim3(32, 64),  256>>>(wff2, t2, 2048, 1024);

    const dim3 gqkv(24, 128);
    const dim3 g1024(8, 128);
    const dim3 g4096(32, 128);

    ln_kernel<<<MROWS, 256>>>(x, ln1_g, ln1_b, lnh, lnl);
    mma_gemm<0,1><<<gqkv, 512, SMEM_MMAGEMM>>>(lnh, lnl, tq, qkv,
        nullptr, nullptr, nullptr, nullptr, MROWS, 1024, 1024);
    attn_kernel<<<dim3(NW, HEADS, BATCH), 256, SMEM_ATTN>>>(q, k, v, relb, ath, atl);
    mma_gemm<2,0><<<g1024, 512, SMEM_MMAGEMM>>>(ath, atl, to, x1,
        bo, x, nullptr, nullptr, MROWS, 1024, 1024);
    ln_kernel<<<MROWS, 256>>>(x1, ln2_g, ln2_b, lnh, lnl);
    mma_gemm<3,0><<<g4096, 512, SMEM_MMAGEMM>>>(lnh, lnl, t1, nullptr,
        bff1, nullptr, hh, hl, MROWS, 4096, 1024);
    mma_gemm<2,0><<<g1024, 512, SMEM_MMAGEMM>>>(hh, hl, t2, out,
        bff2, x1, nullptr, nullptr, MROWS, 1024, 2048);
}

// round 6
// speedup vs baseline: 3.6884x; 1.3549x over previous
#include <cuda_runtime.h>
#include <cuda_bf16.h>
#include <cuda_fp16.h>
#include <math.h>
#include <stdint.h>

// ---------------- problem constants ----------------
#define BATCH 4
#define SEQ   4096
#define DIM   1024
#define HEADS 16
#define HD    64
#define WIN   128
#define NW    (SEQ / WIN)         // 32
#define MROWS (BATCH * SEQ)       // 16384
#define HIDDEN 2048               // = 2*DIM
#define FF1N  (2 * HIDDEN)        // 4096

// ---------------- scratch (device globals; allocation-free) ----------------
static __device__ __align__(128) float g_qkv [(size_t)3 * MROWS * DIM];
static __device__ __align__(128) float g_x1  [(size_t)MROWS * DIM];

static __device__ __align__(128) __half g_lnh [(size_t)MROWS * DIM];
static __device__ __align__(128) __half g_ath [(size_t)MROWS * DIM];
static __device__ __align__(128) __half g_hh  [(size_t)MROWS * HIDDEN];

// transposed fp16 weights [N][K] K-major
// layout: wq @0, wk @1M, wv @2M, wo @3M, ff1(permuted) @4M (4M), ff2 @8M (2M)
#define WT_TOTAL (10u * 1024u * 1024u)
static __device__ __align__(128) __half g_wt[WT_TOTAL];

// ================= helpers =================
__device__ __forceinline__ uint32_t smem_u32(const void* p) {
    uint32_t a;
    asm("{ .reg .u64 t; cvta.to.shared.u64 t, %1; cvt.u32.u64 %0, t; }" : "=r"(a) : "l"(p));
    return a;
}

#define CP_ASYNC16(dst, src) \
    asm volatile("cp.async.cg.shared.global [%0], [%1], 16;" :: "r"(dst), "l"(src))
#define CP_COMMIT() asm volatile("cp.async.commit_group;" ::: "memory")
#define CP_WAIT2()  asm volatile("cp.async.wait_group 2;" ::: "memory")

#define LDSM_X4(r0, r1, r2, r3, addr) \
    asm volatile("ldmatrix.sync.aligned.m8n8.x4.shared.b16 {%0,%1,%2,%3}, [%4];" \
        : "=r"(r0), "=r"(r1), "=r"(r2), "=r"(r3) : "r"(addr))

#define MMA16816(d, a, b) \
    asm volatile("mma.sync.aligned.m16n8k16.row.col.f32.f16.f16.f32 " \
        "{%0,%1,%2,%3}, {%4,%5,%6,%7}, {%8,%9}, {%0,%1,%2,%3};" \
        : "+f"((d)[0]), "+f"((d)[1]), "+f"((d)[2]), "+f"((d)[3]) \
        : "r"((a)[0]), "r"((a)[1]), "r"((a)[2]), "r"((a)[3]), "r"((b)[0]), "r"((b)[1]))

// smem tile: 128 rows x 32 fp16 (64B/row), XOR swizzle on 16B quarters
__device__ __forceinline__ uint32_t swz(int r, int q) {
    return (uint32_t)(r * 64 + ((q ^ ((r >> 1) & 3)) << 4));
}

__device__ __forceinline__ uint2 pack4h(float4 v) {
    __half2 h01 = __float22half2_rn(make_float2(v.x, v.y));
    __half2 h23 = __float22half2_rn(make_float2(v.z, v.w));
    uint2 r;
    r.x = *reinterpret_cast<uint32_t*>(&h01);
    r.y = *reinterpret_cast<uint32_t*>(&h23);
    return r;
}

__device__ __forceinline__ float gelu_exact(float x) {
    return 0.5f * x * (1.f + erff(x * 0.70710678118654752f));
}

// ---------------- LayerNorm -> fp16 ----------------
__global__ void __launch_bounds__(256) ln_kernel(const float* __restrict__ x,
                                                 const float* __restrict__ g,
                                                 const float* __restrict__ b,
                                                 __half* __restrict__ oh)
{
    const int row = blockIdx.x;
    const int tid = threadIdx.x;
    const float4 v = ((const float4*)(x + (size_t)row * DIM))[tid];
    float s  = v.x + v.y + v.z + v.w;
    float ss = v.x*v.x + v.y*v.y + v.z*v.z + v.w*v.w;
    #pragma unroll
    for (int o = 16; o; o >>= 1) {
        s  += __shfl_xor_sync(0xffffffffu, s,  o);
        ss += __shfl_xor_sync(0xffffffffu, ss, o);
    }
    __shared__ float s1[8], s2[8];
    const int w = tid >> 5, l = tid & 31;
    if (l == 0) { s1[w] = s; s2[w] = ss; }
    __syncthreads();
    if (w == 0) {
        s  = (l < 8) ? s1[l] : 0.f;
        ss = (l < 8) ? s2[l] : 0.f;
        #pragma unroll
        for (int o = 4; o; o >>= 1) {
            s  += __shfl_xor_sync(0xffffffffu, s,  o);
            ss += __shfl_xor_sync(0xffffffffu, ss, o);
        }
        if (l == 0) { s1[0] = s * (1.f / DIM); s2[0] = ss * (1.f / DIM); }
    }
    __syncthreads();
    const float m   = s1[0];
    const float var = s2[0] - m * m;
    const float r   = rsqrtf(var + 1e-5f);
    const float4 gv = ((const float4*)g)[tid];
    const float4 bv = ((const float4*)b)[tid];
    float4 o;
    o.x = (v.x - m) * r * gv.x + bv.x;
    o.y = (v.y - m) * r * gv.y + bv.y;
    o.z = (v.z - m) * r * gv.z + bv.z;
    o.w = (v.w - m) * r * gv.w + bv.w;
    ((uint2*)(oh + (size_t)row * DIM))[tid] = pack4h(o);
}

// ---------------- weight transpose: W[K][N] fp32 -> T[N][K] fp16 -----------
// PERM=1: geglu column interleave — output row n' sources W column
//         (n'&1) ? (n'>>1)+HIDDEN : (n'>>1)
template<int PERM>
__global__ void __launch_bounds__(256) wsplit_kernel(const float* __restrict__ W,
    __half* __restrict__ Th, int K, int N)
{
    __shared__ float t[32][33];
    const int n0 = blockIdx.x * 32, k0 = blockIdx.y * 32;
    const int tx = threadIdx.x & 31, ty = threadIdx.x >> 5;
    int sc = n0 + tx;
    if (PERM) sc = (sc & 1) ? (sc >> 1) + HIDDEN : (sc >> 1);
    #pragma unroll
    for (int j = 0; j < 4; ++j)
        t[ty + 8*j][tx] = W[(size_t)(k0 + ty + 8*j) * N + sc];
    __syncthreads();
    #pragma unroll
    for (int j = 0; j < 4; ++j) {
        const float v = t[tx][ty + 8*j];
        Th[(size_t)(n0 + ty + 8*j) * K + k0 + tx] = __float2half_rn(v);
    }
}

// ---------------- HMMA GEMM: C[M,N] = A*B, single fp16 product -------------
// A: fp16 [M][K]; B: fp16 [N][K] (pre-transposed).
// Block 128x128, BK=32, 4-stage cp.async (wait 2), 16 warps (4m x 4n, 32x32).
// EPI: 0 C=AB | 2 C=AB+bias+res | 3 fused geglu -> fp16 (cols halved)
// QKV: if 1, output column-blocks route to q/k/v slabs (each M x 1024).
#define STAGE_BYTES 16384
#define OFF_A  0
#define OFF_B  8192
#define SMEM_MMAGEMM (4 * STAGE_BYTES)   // 65536

template<int EPI, int QKV>
__global__ void __launch_bounds__(512, 1) mma_gemm(
    const __half* __restrict__ A, const __half* __restrict__ B,
    float* __restrict__ C, const float* __restrict__ bias,
    const float* __restrict__ res, __half* __restrict__ Oh,
    int M, int N, int K)
{
    extern __shared__ char smem_raw[];
    const uint32_t sb = smem_u32(smem_raw);
    const int tid = threadIdx.x, lane = tid & 31, warp = tid >> 5;
    const int bxw = blockIdx.x, by = blockIdx.y;
    const int wm = (warp & 3) << 5;   // warp M offset: 0,32,64,96
    const int wn = (warp >> 2) << 5;  // warp N offset: 0,32,64,96

    int bx = bxw;
    if (QKV) {
        C += (size_t)(bxw >> 3) * M * N;   // q/k/v slab
        bx = bxw & 7;
    }

    const __half* Ag = A + (size_t)(by * 128) * K;
    const __half* Bg = B + (size_t)(bxw * 128) * K;

    const int CHUNKS = K >> 5;

    const int rl = tid >> 2, ql = tid & 3;   // 512 threads = 128 rows x 4 quarters

    #define LOAD_CHUNK(c, s) do { \
        const uint32_t st_ = sb + (s) * STAGE_BYTES; \
        const uint32_t o_ = swz(rl, ql); \
        const size_t go_ = (size_t)rl * K + ((c) << 5) + ql * 8; \
        CP_ASYNC16(st_ + OFF_A + o_, Ag + go_); \
        CP_ASYNC16(st_ + OFF_B + o_, Bg + go_); \
    } while (0)

    float acc[2][4][4];
    #pragma unroll
    for (int i = 0; i < 2; ++i)
        #pragma unroll
        for (int j = 0; j < 4; ++j)
            #pragma unroll
            for (int t = 0; t < 4; ++t) acc[i][j][t] = 0.f;

    LOAD_CHUNK(0, 0); CP_COMMIT();
    LOAD_CHUNK(1, 1); CP_COMMIT();
    LOAD_CHUNK(2, 2); CP_COMMIT();

    for (int c = 0; c < CHUNKS; ++c) {
        CP_WAIT2();
        __syncthreads();
        if (c + 3 < CHUNKS) LOAD_CHUNK(c + 3, (c + 3) & 3);
        CP_COMMIT();

        const uint32_t st = sb + (c & 3) * STAGE_BYTES;
        #pragma unroll
        for (int ks = 0; ks < 2; ++ks) {
            uint32_t af[2][4];
            #pragma unroll
            for (int mt = 0; mt < 2; ++mt) {
                const int row = wm + mt * 16 + (lane & 15);
                const int q   = (ks << 1) + (lane >> 4);
                const uint32_t off = swz(row, q);
                LDSM_X4(af[mt][0], af[mt][1], af[mt][2], af[mt][3], st + OFF_A + off);
            }
            uint32_t bf[4][2];
            #pragma unroll
            for (int np = 0; np < 2; ++np) {
                const int row = wn + np * 16 + (lane & 7) + ((lane >> 4) << 3);
                const int q   = (ks << 1) + ((lane >> 3) & 1);
                const uint32_t off = swz(row, q);
                uint32_t t0, t1, t2, t3;
                LDSM_X4(t0, t1, t2, t3, st + OFF_B + off);
                bf[2*np][0] = t0;   bf[2*np][1] = t1;
                bf[2*np+1][0] = t2; bf[2*np+1][1] = t3;
            }
            #pragma unroll
            for (int mt = 0; mt < 2; ++mt)
                #pragma unroll
                for (int nt = 0; nt < 4; ++nt)
                    MMA16816(acc[mt][nt], af[mt], bf[nt]);
        }
    }

    if (EPI == 3) {
        // fused GEGLU: even col = val_j, odd col = gate_j, j = col>>1
        #pragma unroll
        for (int mt = 0; mt < 2; ++mt) {
            const int gr = by * 128 + wm + mt * 16 + (lane >> 2);
            #pragma unroll
            for (int nt = 0; nt < 4; ++nt) {
                const int col = bx * 128 + wn + nt * 8 + ((lane & 3) << 1);
                const int j = col >> 1;
                const float bv = bias[j];
                const float bg = bias[j + HIDDEN];
                const float h0 = (acc[mt][nt][0] + bv) * gelu_exact(acc[mt][nt][1] + bg);
                const float h1 = (acc[mt][nt][2] + bv) * gelu_exact(acc[mt][nt][3] + bg);
                Oh[(size_t)gr * HIDDEN + j]       = __float2half_rn(h0);
                Oh[(size_t)(gr + 8) * HIDDEN + j] = __float2half_rn(h1);
            }
        }
    } else {
        #pragma unroll
        for (int mt = 0; mt < 2; ++mt) {
            const int gr = by * 128 + wm + mt * 16 + (lane >> 2);
            #pragma unroll
            for (int nt = 0; nt < 4; ++nt) {
                const int col = bx * 128 + wn + nt * 8 + ((lane & 3) << 1);
                float2 v0 = make_float2(acc[mt][nt][0], acc[mt][nt][1]);
                float2 v1 = make_float2(acc[mt][nt][2], acc[mt][nt][3]);
                if (EPI >= 1) {
                    const float2 bb = *(const float2*)(bias + col);
                    v0.x += bb.x; v0.y += bb.y; v1.x += bb.x; v1.y += bb.y;
                }
                if (EPI == 2) {
                    const float2 r0v = *(const float2*)(res + (size_t)gr * N + col);
                    const float2 r1v = *(const float2*)(res + (size_t)(gr + 8) * N + col);
                    v0.x += r0v.x; v0.y += r0v.y; v1.x += r1v.x; v1.y += r1v.y;
                }
                *(float2*)(C + (size_t)gr * N + col) = v0;
                *(float2*)(C + (size_t)(gr + 8) * N + col) = v1;
            }
        }
    }
    #undef LOAD_CHUNK
}

// ---------------- Sliding-window attention (fp32) -> fp16 out --------------
#define SMEM_ATTN ((64*128 + 64*256 + 128*256 + 256) * 4)

__global__ void __launch_bounds__(256) attn_kernel(
    const float* __restrict__ q, const float* __restrict__ k,
    const float* __restrict__ v, const float* __restrict__ rel_bias,
    __half* __restrict__ outh)
{
    const int n = blockIdx.x;
    const int h = blockIdx.y;
    const int b = blockIdx.z;
    extern __shared__ float smf[];
    float* qT = smf;
    float* kT = smf + 64 * 128;
    float* P  = smf + 64 * 128 + 64 * 256;
    float* bs = P + 128 * 256;
    const int tid = threadIdx.x;

    bs[tid] = rel_bias[h * 256 + tid];

    const long long qbase = ((long long)(b * SEQ + n * WIN)) * DIM + h * HD;
    for (int t = tid; t < 128 * 16; t += 256) {
        const int i = t >> 4, d4 = (t & 15) << 2;
        float4 val = *(const float4*)(q + qbase + (long long)i * DIM + d4);
        qT[(d4 + 0) * 128 + i] = val.x * 0.125f;
        qT[(d4 + 1) * 128 + i] = val.y * 0.125f;
        qT[(d4 + 2) * 128 + i] = val.z * 0.125f;
        qT[(d4 + 3) * 128 + i] = val.w * 0.125f;
    }
    const long long kbase = ((long long)(b * SEQ + n * WIN - WIN)) * DIM + h * HD;
    for (int t = tid; t < 256 * 16; t += 256) {
        const int j = t >> 4, d4 = (t & 15) << 2;
        float4 val = make_float4(0.f, 0.f, 0.f, 0.f);
        if (!(n == 0 && j < 128))
            val = *(const float4*)(k + kbase + (long long)j * DIM + d4);
        kT[(d4 + 0) * 256 + j] = val.x;
        kT[(d4 + 1) * 256 + j] = val.y;
        kT[(d4 + 2) * 256 + j] = val.z;
        kT[(d4 + 3) * 256 + j] = val.w;
    }
    __syncthreads();

    const int jc  = (tid & 63) << 2;
    const int rgb = tid >> 6;
    for (int it = 0; it < 4; ++it) {
        const int i0 = (it * 4 + rgb) * 8;
        float acc[8][4] = {};
        #pragma unroll 4
        for (int d = 0; d < 64; ++d) {
            float4 a0 = *(float4*)&qT[d * 128 + i0];
            float4 a1 = *(float4*)&qT[d * 128 + i0 + 4];
            float4 kv = *(float4*)&kT[d * 256 + jc];
            float ar[8] = {a0.x,a0.y,a0.z,a0.w,a1.x,a1.y,a1.z,a1.w};
            float kr[4] = {kv.x,kv.y,kv.z,kv.w};
            #pragma unroll
            for (int r = 0; r < 8; ++r)
                #pragma unroll
                for (int cJ = 0; cJ < 4; ++cJ)
                    acc[r][cJ] += ar[r] * kr[cJ];
        }
        #pragma unroll
        for (int r = 0; r < 8; ++r) {
            const int i = i0 + r;
            float4 o;
            float* oc = (float*)&o;
            #pragma unroll
            for (int cJ = 0; cJ < 4; ++cJ) {
                const int j = jc + cJ;
                const int dist = i + WIN - j;
                const bool valid = (dist >= 0) && (n > 0 || j >= WIN);
                oc[cJ] = valid ? (acc[r][cJ] + bs[dist]) : -1e9f;
            }
            *(float4*)&P[i * 256 + jc] = o;
        }
    }
    __syncthreads();

    const int wid = tid >> 5, lane = tid & 31;
    for (int i = wid; i < 128; i += 8) {
        float vals[8];
        float mx = -1e30f;
        #pragma unroll
        for (int t2 = 0; t2 < 8; ++t2) {
            vals[t2] = P[i * 256 + lane + 32 * t2];
            mx = fmaxf(mx, vals[t2]);
        }
        #pragma unroll
        for (int o = 16; o; o >>= 1) mx = fmaxf(mx, __shfl_xor_sync(0xffffffffu, mx, o));
        float sum = 0.f;
        #pragma unroll
        for (int t2 = 0; t2 < 8; ++t2) { vals[t2] = __expf(vals[t2] - mx); sum += vals[t2]; }
        #pragma unroll
        for (int o = 16; o; o >>= 1) sum += __shfl_xor_sync(0xffffffffu, sum, o);
        const float inv = 1.f / sum;
        #pragma unroll
        for (int t2 = 0; t2 < 8; ++t2) P[i * 256 + lane + 32 * t2] = vals[t2] * inv;
    }
    __syncthreads();

    float* vs = kT;
    for (int t = tid; t < 256 * 16; t += 256) {
        const int j = t >> 4, d4 = (t & 15) << 2;
        float4 val = make_float4(0.f, 0.f, 0.f, 0.f);
        if (!(n == 0 && j < 128))
            val = *(const float4*)(v + kbase + (long long)j * DIM + d4);
        *(float4*)&vs[j * 64 + d4] = val;
    }
    __syncthreads();

    const int dc  = (tid & 15) << 2;
    const int rg2 = tid >> 4;
    for (int it = 0; it < 2; ++it) {
        const int i0 = (it * 16 + rg2) * 4;
        float acc[4][4] = {};
        #pragma unroll 4
        for (int j = 0; j < 256; ++j) {
            float4 vv = *(float4*)&vs[j * 64 + dc];
            float vr[4] = {vv.x, vv.y, vv.z, vv.w};
            float p0 = P[(i0 + 0) * 256 + j];
            float p1 = P[(i0 + 1) * 256 + j];
            float p2 = P[(i0 + 2) * 256 + j];
            float p3 = P[(i0 + 3) * 256 + j];
            #pragma unroll
            for (int cc = 0; cc < 4; ++cc) {
                acc[0][cc] += p0 * vr[cc];
                acc[1][cc] += p1 * vr[cc];
                acc[2][cc] += p2 * vr[cc];
                acc[3][cc] += p3 * vr[cc];
            }
        }
        #pragma unroll
        for (int r = 0; r < 4; ++r) {
            float4 o = make_float4(acc[r][0], acc[r][1], acc[r][2], acc[r][3]);
            *(uint2*)(outh + qbase + (long long)(i0 + r) * DIM + dc) = pack4h(o);
        }
    }
}

// ---------------- launch ----------------
extern "C" void kernel_launch(void* const* d_in, const int* in_sizes, int n_in,
                              void* d_out, int out_size)
{
    const float* x     = (const float*)d_in[0];
    const float* ln1_g = (const float*)d_in[1];
    const float* ln1_b = (const float*)d_in[2];
    const float* ln2_g = (const float*)d_in[3];
    const float* ln2_b = (const float*)d_in[4];
    const float* wq    = (const float*)d_in[5];
    const float* wk    = (const float*)d_in[6];
    const float* wv    = (const float*)d_in[7];
    const float* wo    = (const float*)d_in[8];
    const float* bo    = (const float*)d_in[9];
    const float* relb  = (const float*)d_in[10];
    const float* wff1  = (const float*)d_in[11];
    const float* bff1  = (const float*)d_in[12];
    const float* wff2  = (const float*)d_in[13];
    const float* bff2  = (const float*)d_in[14];
    float* out = (float*)d_out;

    float *qkv, *x1;
    __half *lnh, *ath, *hh, *wt;
    cudaGetSymbolAddress((void**)&qkv,  g_qkv);
    cudaGetSymbolAddress((void**)&x1,   g_x1);
    cudaGetSymbolAddress((void**)&lnh,  g_lnh);
    cudaGetSymbolAddress((void**)&ath,  g_ath);
    cudaGetSymbolAddress((void**)&hh,   g_hh);
    cudaGetSymbolAddress((void**)&wt,   g_wt);

    float* q = qkv;
    float* k = qkv + (size_t)MROWS * DIM;
    float* v = qkv + (size_t)2 * MROWS * DIM;

    cudaFuncSetAttribute(attn_kernel, cudaFuncAttributeMaxDynamicSharedMemorySize, SMEM_ATTN);
    cudaFuncSetAttribute((mma_gemm<0,1>), cudaFuncAttributeMaxDynamicSharedMemorySize, SMEM_MMAGEMM);
    cudaFuncSetAttribute((mma_gemm<2,0>), cudaFuncAttributeMaxDynamicSharedMemorySize, SMEM_MMAGEMM);
    cudaFuncSetAttribute((mma_gemm<3,0>), cudaFuncAttributeMaxDynamicSharedMemorySize, SMEM_MMAGEMM);

    const size_t OW = (size_t)1024 * 1024;
    __half *tq = wt;           // q,k,v stacked
    __half *to = wt + 3*OW;
    __half *t1 = wt + 4*OW;    // ff1 permuted: 4M elems
    __half *t2 = wt + 8*OW;    // ff2: 2M elems

    wsplit_kernel<0><<<dim3(32, 32),  256>>>(wq,   tq,        1024, 1024);
    wsplit_kernel<0><<<dim3(32, 32),  256>>>(wk,   wt + OW,   1024, 1024);
    wsplit_kernel<0><<<dim3(32, 32),  256>>>(wv,   wt + 2*OW, 1024, 1024);
    wsplit_kernel<0><<<dim3(32, 32),  256>>>(wo,   to,        1024, 1024);
    wsplit_kernel<1><<<dim3(128, 32), 256>>>(wff1, t1,        1024, 4096);
    wsplit_kernel<0><<<dim3(32, 64),  256>>>(wff2, t2,        2048, 1024);

    const dim3 gqkv(24, 128);
    const dim3 g1024(8, 128);
    const dim3 g4096(32, 128);

    ln_kernel<<<MROWS, 256>>>(x, ln1_g, ln1_b, lnh);
    mma_gemm<0,1><<<gqkv, 512, SMEM_MMAGEMM>>>(lnh, tq, qkv,
        nullptr, nullptr, nullptr, MROWS, 1024, 1024);
    attn_kernel<<<dim3(NW, HEADS, BATCH), 256, SMEM_ATTN>>>(q, k, v, relb, ath);
    mma_gemm<2,0><<<g1024, 512, SMEM_MMAGEMM>>>(ath, to, x1,
        bo, x, nullptr, MROWS, 1024, 1024);
    ln_kernel<<<MROWS, 256>>>(x1, ln2_g, ln2_b, lnh);
    mma_gemm<3,0><<<g4096, 512, SMEM_MMAGEMM>>>(lnh, t1, nullptr,
        bff1, nullptr, hh, MROWS, 4096, 1024);
    mma_gemm<2,0><<<g1024, 512, SMEM_MMAGEMM>>>(hh, t2, out,
        bff2, x1, nullptr, MROWS, 1024, 2048);
}

// round 7
// speedup vs baseline: 5.2667x; 1.4279x over previous
#include <cuda_runtime.h>
#include <cuda_bf16.h>
#include <cuda_fp16.h>
#include <math.h>
#include <stdint.h>

// ---------------- problem constants ----------------
#define BATCH 4
#define SEQ   4096
#define DIM   1024
#define HEADS 16
#define HD    64
#define WIN   128
#define NW    (SEQ / WIN)         // 32
#define MROWS (BATCH * SEQ)       // 16384
#define HIDDEN 2048               // = 2*DIM
#define FF1N  (2 * HIDDEN)        // 4096

// ---------------- scratch (device globals; allocation-free) ----------------
static __device__ __align__(128) float g_x1  [(size_t)MROWS * DIM];

static __device__ __align__(128) __half g_lnh [(size_t)MROWS * DIM];
static __device__ __align__(128) __half g_ath [(size_t)MROWS * DIM];
static __device__ __align__(128) __half g_hh  [(size_t)MROWS * HIDDEN];
static __device__ __align__(128) __half g_qkvh[(size_t)3 * MROWS * DIM];
static __device__ __align__(128) __half g_vT  [(size_t)DIM * MROWS];

// transposed fp16 weights [N][K] K-major
#define WT_TOTAL (10u * 1024u * 1024u)
static __device__ __align__(128) __half g_wt[WT_TOTAL];

// ================= helpers =================
__device__ __forceinline__ uint32_t smem_u32(const void* p) {
    uint32_t a;
    asm("{ .reg .u64 t; cvta.to.shared.u64 t, %1; cvt.u32.u64 %0, t; }" : "=r"(a) : "l"(p));
    return a;
}

#define CP_ASYNC16(dst, src) \
    asm volatile("cp.async.cg.shared.global [%0], [%1], 16;" :: "r"(dst), "l"(src))
#define CP_COMMIT() asm volatile("cp.async.commit_group;" ::: "memory")
#define CP_WAIT2()  asm volatile("cp.async.wait_group 2;" ::: "memory")
#define CP_WAIT0()  asm volatile("cp.async.wait_group 0;" ::: "memory")

#define LDSM_X4(r0, r1, r2, r3, addr) \
    asm volatile("ldmatrix.sync.aligned.m8n8.x4.shared.b16 {%0,%1,%2,%3}, [%4];" \
        : "=r"(r0), "=r"(r1), "=r"(r2), "=r"(r3) : "r"(addr))

#define MMA16816(d, a, b) \
    asm volatile("mma.sync.aligned.m16n8k16.row.col.f32.f16.f16.f32 " \
        "{%0,%1,%2,%3}, {%4,%5,%6,%7}, {%8,%9}, {%0,%1,%2,%3};" \
        : "+f"((d)[0]), "+f"((d)[1]), "+f"((d)[2]), "+f"((d)[3]) \
        : "r"((a)[0]), "r"((a)[1]), "r"((a)[2]), "r"((a)[3]), "r"((b)[0]), "r"((b)[1]))

// smem tile: rows x 32 fp16 (64B/row), XOR swizzle on 16B quarters
__device__ __forceinline__ uint32_t swz(int r, int q) {
    return (uint32_t)(r * 64 + ((q ^ ((r >> 1) & 3)) << 4));
}

__device__ __forceinline__ uint2 pack4h(float4 v) {
    __half2 h01 = __float22half2_rn(make_float2(v.x, v.y));
    __half2 h23 = __float22half2_rn(make_float2(v.z, v.w));
    uint2 r;
    r.x = *reinterpret_cast<uint32_t*>(&h01);
    r.y = *reinterpret_cast<uint32_t*>(&h23);
    return r;
}

__device__ __forceinline__ float gelu_exact(float x) {
    return 0.5f * x * (1.f + erff(x * 0.70710678118654752f));
}

// ---------------- LayerNorm -> fp16 ----------------
__global__ void __launch_bounds__(256) ln_kernel(const float* __restrict__ x,
                                                 const float* __restrict__ g,
                                                 const float* __restrict__ b,
                                                 __half* __restrict__ oh)
{
    const int row = blockIdx.x;
    const int tid = threadIdx.x;
    const float4 v = ((const float4*)(x + (size_t)row * DIM))[tid];
    float s  = v.x + v.y + v.z + v.w;
    float ss = v.x*v.x + v.y*v.y + v.z*v.z + v.w*v.w;
    #pragma unroll
    for (int o = 16; o; o >>= 1) {
        s  += __shfl_xor_sync(0xffffffffu, s,  o);
        ss += __shfl_xor_sync(0xffffffffu, ss, o);
    }
    __shared__ float s1[8], s2[8];
    const int w = tid >> 5, l = tid & 31;
    if (l == 0) { s1[w] = s; s2[w] = ss; }
    __syncthreads();
    if (w == 0) {
        s  = (l < 8) ? s1[l] : 0.f;
        ss = (l < 8) ? s2[l] : 0.f;
        #pragma unroll
        for (int o = 4; o; o >>= 1) {
            s  += __shfl_xor_sync(0xffffffffu, s,  o);
            ss += __shfl_xor_sync(0xffffffffu, ss, o);
        }
        if (l == 0) { s1[0] = s * (1.f / DIM); s2[0] = ss * (1.f / DIM); }
    }
    __syncthreads();
    const float m   = s1[0];
    const float var = s2[0] - m * m;
    const float r   = rsqrtf(var + 1e-5f);
    const float4 gv = ((const float4*)g)[tid];
    const float4 bv = ((const float4*)b)[tid];
    float4 o;
    o.x = (v.x - m) * r * gv.x + bv.x;
    o.y = (v.y - m) * r * gv.y + bv.y;
    o.z = (v.z - m) * r * gv.z + bv.z;
    o.w = (v.w - m) * r * gv.w + bv.w;
    ((uint2*)(oh + (size_t)row * DIM))[tid] = pack4h(o);
}

// ---------------- weight transpose: W[K][N] fp32 -> T[N][K] fp16 -----------
template<int PERM>
__global__ void __launch_bounds__(256) wsplit_kernel(const float* __restrict__ W,
    __half* __restrict__ Th, int K, int N)
{
    __shared__ float t[32][33];
    const int n0 = blockIdx.x * 32, k0 = blockIdx.y * 32;
    const int tx = threadIdx.x & 31, ty = threadIdx.x >> 5;
    int sc = n0 + tx;
    if (PERM) sc = (sc & 1) ? (sc >> 1) + HIDDEN : (sc >> 1);
    #pragma unroll
    for (int j = 0; j < 4; ++j)
        t[ty + 8*j][tx] = W[(size_t)(k0 + ty + 8*j) * N + sc];
    __syncthreads();
    #pragma unroll
    for (int j = 0; j < 4; ++j) {
        const float v = t[tx][ty + 8*j];
        Th[(size_t)(n0 + ty + 8*j) * K + k0 + tx] = __float2half_rn(v);
    }
}

// ---------------- fp16 transpose: V[MROWS][DIM] -> vT[DIM][MROWS] ----------
__global__ void __launch_bounds__(256) vtrans_kernel(const __half* __restrict__ V,
                                                     __half* __restrict__ vT)
{
    __shared__ __half t[32][33];
    const int c0 = blockIdx.x * 32, r0 = blockIdx.y * 32;
    const int tx = threadIdx.x & 31, ty = threadIdx.x >> 5;
    #pragma unroll
    for (int j = 0; j < 4; ++j)
        t[ty + 8*j][tx] = V[(size_t)(r0 + ty + 8*j) * DIM + c0 + tx];
    __syncthreads();
    #pragma unroll
    for (int j = 0; j < 4; ++j)
        vT[(size_t)(c0 + ty + 8*j) * MROWS + r0 + tx] = t[tx][ty + 8*j];
}

// ---------------- HMMA GEMM: C[M,N] = A*B, single fp16 product -------------
// EPI: 0 C=AB | 2 C=AB+bias+res | 3 fused geglu -> fp16 | 4 fp16 out (+q scale)
#define STAGE_BYTES 16384
#define OFF_A  0
#define OFF_B  8192
#define SMEM_MMAGEMM (4 * STAGE_BYTES)   // 65536

template<int EPI, int QKV>
__global__ void __launch_bounds__(512, 1) mma_gemm(
    const __half* __restrict__ A, const __half* __restrict__ B,
    float* __restrict__ C, const float* __restrict__ bias,
    const float* __restrict__ res, __half* __restrict__ Oh,
    int M, int N, int K)
{
    extern __shared__ char smem_raw[];
    const uint32_t sb = smem_u32(smem_raw);
    const int tid = threadIdx.x, lane = tid & 31, warp = tid >> 5;
    const int bxw = blockIdx.x, by = blockIdx.y;
    const int wm = (warp & 3) << 5;
    const int wn = (warp >> 2) << 5;

    int bx = bxw;
    if (QKV) {
        if (EPI == 4) Oh += (size_t)(bxw >> 3) * M * N;
        else          C  += (size_t)(bxw >> 3) * M * N;
        bx = bxw & 7;
    }

    const __half* Ag = A + (size_t)(by * 128) * K;
    const __half* Bg = B + (size_t)(bxw * 128) * K;

    const int CHUNKS = K >> 5;
    const int rl = tid >> 2, ql = tid & 3;

    #define LOAD_CHUNK(c, s) do { \
        const uint32_t st_ = sb + (s) * STAGE_BYTES; \
        const uint32_t o_ = swz(rl, ql); \
        const size_t go_ = (size_t)rl * K + ((c) << 5) + ql * 8; \
        CP_ASYNC16(st_ + OFF_A + o_, Ag + go_); \
        CP_ASYNC16(st_ + OFF_B + o_, Bg + go_); \
    } while (0)

    float acc[2][4][4];
    #pragma unroll
    for (int i = 0; i < 2; ++i)
        #pragma unroll
        for (int j = 0; j < 4; ++j)
            #pragma unroll
            for (int t = 0; t < 4; ++t) acc[i][j][t] = 0.f;

    LOAD_CHUNK(0, 0); CP_COMMIT();
    LOAD_CHUNK(1, 1); CP_COMMIT();
    LOAD_CHUNK(2, 2); CP_COMMIT();

    for (int c = 0; c < CHUNKS; ++c) {
        CP_WAIT2();
        __syncthreads();
        if (c + 3 < CHUNKS) LOAD_CHUNK(c + 3, (c + 3) & 3);
        CP_COMMIT();

        const uint32_t st = sb + (c & 3) * STAGE_BYTES;
        #pragma unroll
        for (int ks = 0; ks < 2; ++ks) {
            uint32_t af[2][4];
            #pragma unroll
            for (int mt = 0; mt < 2; ++mt) {
                const int row = wm + mt * 16 + (lane & 15);
                const int q   = (ks << 1) + (lane >> 4);
                LDSM_X4(af[mt][0], af[mt][1], af[mt][2], af[mt][3],
                        st + OFF_A + swz(row, q));
            }
            uint32_t bf[4][2];
            #pragma unroll
            for (int np = 0; np < 2; ++np) {
                const int row = wn + np * 16 + (lane & 7) + ((lane >> 4) << 3);
                const int q   = (ks << 1) + ((lane >> 3) & 1);
                uint32_t t0, t1, t2, t3;
                LDSM_X4(t0, t1, t2, t3, st + OFF_B + swz(row, q));
                bf[2*np][0] = t0;   bf[2*np][1] = t1;
                bf[2*np+1][0] = t2; bf[2*np+1][1] = t3;
            }
            #pragma unroll
            for (int mt = 0; mt < 2; ++mt)
                #pragma unroll
                for (int nt = 0; nt < 4; ++nt)
                    MMA16816(acc[mt][nt], af[mt], bf[nt]);
        }
    }

    if (EPI == 3) {
        #pragma unroll
        for (int mt = 0; mt < 2; ++mt) {
            const int gr = by * 128 + wm + mt * 16 + (lane >> 2);
            #pragma unroll
            for (int nt = 0; nt < 4; ++nt) {
                const int col = bx * 128 + wn + nt * 8 + ((lane & 3) << 1);
                const int j = col >> 1;
                const float bv = bias[j];
                const float bg = bias[j + HIDDEN];
                const float h0 = (acc[mt][nt][0] + bv) * gelu_exact(acc[mt][nt][1] + bg);
                const float h1 = (acc[mt][nt][2] + bv) * gelu_exact(acc[mt][nt][3] + bg);
                Oh[(size_t)gr * HIDDEN + j]       = __float2half_rn(h0);
                Oh[(size_t)(gr + 8) * HIDDEN + j] = __float2half_rn(h1);
            }
        }
    } else if (EPI == 4) {
        const float sc = (QKV && (bxw >> 3) == 0) ? 0.125f : 1.0f;
        #pragma unroll
        for (int mt = 0; mt < 2; ++mt) {
            const int gr = by * 128 + wm + mt * 16 + (lane >> 2);
            #pragma unroll
            for (int nt = 0; nt < 4; ++nt) {
                const int col = bx * 128 + wn + nt * 8 + ((lane & 3) << 1);
                __half2 o0 = __float22half2_rn(make_float2(acc[mt][nt][0]*sc, acc[mt][nt][1]*sc));
                __half2 o1 = __float22half2_rn(make_float2(acc[mt][nt][2]*sc, acc[mt][nt][3]*sc));
                *(__half2*)(Oh + (size_t)gr * N + col) = o0;
                *(__half2*)(Oh + (size_t)(gr + 8) * N + col) = o1;
            }
        }
    } else {
        #pragma unroll
        for (int mt = 0; mt < 2; ++mt) {
            const int gr = by * 128 + wm + mt * 16 + (lane >> 2);
            #pragma unroll
            for (int nt = 0; nt < 4; ++nt) {
                const int col = bx * 128 + wn + nt * 8 + ((lane & 3) << 1);
                float2 v0 = make_float2(acc[mt][nt][0], acc[mt][nt][1]);
                float2 v1 = make_float2(acc[mt][nt][2], acc[mt][nt][3]);
                if (EPI >= 1) {
                    const float2 bb = *(const float2*)(bias + col);
                    v0.x += bb.x; v0.y += bb.y; v1.x += bb.x; v1.y += bb.y;
                }
                if (EPI == 2) {
                    const float2 r0v = *(const float2*)(res + (size_t)gr * N + col);
                    const float2 r1v = *(const float2*)(res + (size_t)(gr + 8) * N + col);
                    v0.x += r0v.x; v0.y += r0v.y; v1.x += r1v.x; v1.y += r1v.y;
                }
                *(float2*)(C + (size_t)gr * N + col) = v0;
                *(float2*)(C + (size_t)(gr + 8) * N + col) = v1;
            }
        }
    }
    #undef LOAD_CHUNK
}

// ---------------- HMMA sliding-window attention -----------------------------
// block = (window n, head h, batch b); 512 threads / 16 warps.
// smem: Q [2 chunks][128][32]h | K [2][256][32]h | Vt [8][64][32]h |
//       P [8][128][32]h | bias 256f | red 4x128f | invsum 128f
#define AQ 0
#define AK 16384
#define AV 49152
#define AP 81920
#define ABIAS 147456
#define ARED  148480
#define ASUM  150528
#define SMEM_ATTN2 151040

__global__ void __launch_bounds__(512, 1) attn_mma(
    const __half* __restrict__ q, const __half* __restrict__ k,
    const __half* __restrict__ vT, const float* __restrict__ rel_bias,
    __half* __restrict__ outh)
{
    extern __shared__ char smc[];
    const uint32_t sb = smem_u32(smc);
    const int n = blockIdx.x, h = blockIdx.y, b = blockIdx.z;
    const int tid = threadIdx.x, lane = tid & 31, warp = tid >> 5;
    const size_t row0 = (size_t)b * SEQ + (size_t)n * WIN;

    float* bsf  = (float*)(smc + ABIAS);
    float* redf = (float*)(smc + ARED);
    float* sumf = (float*)(smc + ASUM);

    // ---- async loads: Q, K, Vt ----
    #pragma unroll
    for (int i = 0; i < 2; ++i) {
        const int row = tid >> 2, Q4 = (tid & 3) + 4 * i;
        const uint32_t off = AQ + (Q4 >> 2) * 8192 + swz(row, Q4 & 3);
        CP_ASYNC16(sb + off, q + (row0 + row) * DIM + h * HD + Q4 * 8);
    }
    #pragma unroll
    for (int i = 0; i < 4; ++i) {
        const int row = (tid >> 2) + 128 * (i >> 1);
        const int Q4 = (tid & 3) + 4 * (i & 1);
        const uint32_t off = AK + (Q4 >> 2) * 16384 + swz(row, Q4 & 3);
        if (n == 0 && row < 128)
            *(uint4*)(smc + off) = make_uint4(0, 0, 0, 0);
        else
            CP_ASYNC16(sb + off, k + (row0 - WIN + row) * DIM + h * HD + Q4 * 8);
    }
    #pragma unroll
    for (int i = 0; i < 4; ++i) {
        const int d = tid >> 3, J4 = (tid & 7) + 8 * i;
        const uint32_t off = AV + (J4 >> 2) * 4096 + swz(d, J4 & 3);
        if (n == 0 && J4 < 16)
            *(uint4*)(smc + off) = make_uint4(0, 0, 0, 0);
        else
            CP_ASYNC16(sb + off, vT + (size_t)(h * HD + d) * MROWS + row0 - WIN + J4 * 8);
    }
    if (tid < 256) bsf[tid] = rel_bias[h * 256 + tid];
    CP_COMMIT();
    CP_WAIT0();
    __syncthreads();

    // ---- S = Q @ K^T : 16 warps, warp tile 32x64 ----
    const int wm  = (warp & 3) << 5;    // 0,32,64,96
    const int wnS = (warp >> 2) << 6;   // 0,64,128,192
    const int wnIdx = warp >> 2;

    float acc[2][8][4];
    #pragma unroll
    for (int i = 0; i < 2; ++i)
        #pragma unroll
        for (int j = 0; j < 8; ++j)
            #pragma unroll
            for (int t = 0; t < 4; ++t) acc[i][j][t] = 0.f;

    #pragma unroll
    for (int kc = 0; kc < 2; ++kc)
        #pragma unroll
        for (int ks = 0; ks < 2; ++ks) {
            uint32_t af[2][4];
            #pragma unroll
            for (int mt = 0; mt < 2; ++mt) {
                const int row = wm + mt * 16 + (lane & 15);
                const int qq  = (ks << 1) + (lane >> 4);
                LDSM_X4(af[mt][0], af[mt][1], af[mt][2], af[mt][3],
                        sb + AQ + kc * 8192 + swz(row, qq));
            }
            uint32_t bf[8][2];
            #pragma unroll
            for (int np = 0; np < 4; ++np) {
                const int row = wnS + np * 16 + (lane & 7) + ((lane >> 4) << 3);
                const int qq  = (ks << 1) + ((lane >> 3) & 1);
                uint32_t t0, t1, t2, t3;
                LDSM_X4(t0, t1, t2, t3, sb + AK + kc * 16384 + swz(row, qq));
                bf[2*np][0] = t0;   bf[2*np][1] = t1;
                bf[2*np+1][0] = t2; bf[2*np+1][1] = t3;
            }
            #pragma unroll
            for (int mt = 0; mt < 2; ++mt)
                #pragma unroll
                for (int nt = 0; nt < 8; ++nt)
                    MMA16816(acc[mt][nt], af[mt], bf[nt]);
        }

    // ---- mask + bias + row max ----
    float mxv[2][2];
    #pragma unroll
    for (int mt = 0; mt < 2; ++mt)
        #pragma unroll
        for (int h2 = 0; h2 < 2; ++h2) {
            const int row = wm + mt * 16 + (lane >> 2) + h2 * 8;
            float m = -1e30f;
            #pragma unroll
            for (int nt = 0; nt < 8; ++nt) {
                const int c0 = wnS + nt * 8;
                const bool dead = (c0 > wm + mt * 16 + 143) ||
                                  (n == 0 && c0 + 8 <= 128);
                if (dead) {
                    acc[mt][nt][h2*2+0] = -1e30f;
                    acc[mt][nt][h2*2+1] = -1e30f;
                    continue;
                }
                #pragma unroll
                for (int cc = 0; cc < 2; ++cc) {
                    const int col = c0 + ((lane & 3) << 1) + cc;
                    const int e = h2 * 2 + cc;
                    const int dist = row + WIN - col;
                    const bool valid = (dist >= 0) && (n > 0 || col >= WIN);
                    const float s = valid ? (acc[mt][nt][e] + bsf[dist]) : -1e30f;
                    acc[mt][nt][e] = s;
                    m = fmaxf(m, s);
                }
            }
            mxv[mt][h2] = m;
        }
    #pragma unroll
    for (int mt = 0; mt < 2; ++mt)
        #pragma unroll
        for (int h2 = 0; h2 < 2; ++h2) {
            mxv[mt][h2] = fmaxf(mxv[mt][h2], __shfl_xor_sync(0xffffffffu, mxv[mt][h2], 1));
            mxv[mt][h2] = fmaxf(mxv[mt][h2], __shfl_xor_sync(0xffffffffu, mxv[mt][h2], 2));
        }
    if ((lane & 3) == 0) {
        #pragma unroll
        for (int mt = 0; mt < 2; ++mt)
            #pragma unroll
            for (int h2 = 0; h2 < 2; ++h2)
                redf[wnIdx * 128 + wm + mt * 16 + (lane >> 2) + h2 * 8] = mxv[mt][h2];
    }
    __syncthreads();
    #pragma unroll
    for (int mt = 0; mt < 2; ++mt)
        #pragma unroll
        for (int h2 = 0; h2 < 2; ++h2) {
            const int row = wm + mt * 16 + (lane >> 2) + h2 * 8;
            float m = redf[row];
            m = fmaxf(m, redf[128 + row]);
            m = fmaxf(m, redf[256 + row]);
            m = fmaxf(m, redf[384 + row]);
            mxv[mt][h2] = m;
        }
    __syncthreads();

    // ---- exp (skip dead tiles), store fp16 P, row sums ----
    float smv[2][2];
    #pragma unroll
    for (int mt = 0; mt < 2; ++mt)
        #pragma unroll
        for (int h2 = 0; h2 < 2; ++h2) {
            const int row = wm + mt * 16 + (lane >> 2) + h2 * 8;
            const float m = mxv[mt][h2];
            float rs = 0.f;
            #pragma unroll
            for (int nt = 0; nt < 8; ++nt) {
                const int c0 = wnS + nt * 8;
                const int col = c0 + ((lane & 3) << 1);
                const int c5 = col & 31;
                const uint32_t off = AP + (col >> 5) * 8192 + row * 64 +
                    ((((c5 >> 3)) ^ ((row >> 1) & 3)) << 4) + (c5 & 7) * 2;
                const bool dead = (c0 > wm + mt * 16 + 143) ||
                                  (n == 0 && c0 + 8 <= 128);
                if (dead) {
                    *(__half2*)(smc + off) = __float2half2_rn(0.f);
                } else {
                    const float p0 = __expf(acc[mt][nt][h2*2+0] - m);
                    const float p1 = __expf(acc[mt][nt][h2*2+1] - m);
                    rs += p0 + p1;
                    *(__half2*)(smc + off) = __float22half2_rn(make_float2(p0, p1));
                }
            }
            smv[mt][h2] = rs;
        }
    #pragma unroll
    for (int mt = 0; mt < 2; ++mt)
        #pragma unroll
        for (int h2 = 0; h2 < 2; ++h2) {
            smv[mt][h2] += __shfl_xor_sync(0xffffffffu, smv[mt][h2], 1);
            smv[mt][h2] += __shfl_xor_sync(0xffffffffu, smv[mt][h2], 2);
        }
    if ((lane & 3) == 0) {
        #pragma unroll
        for (int mt = 0; mt < 2; ++mt)
            #pragma unroll
            for (int h2 = 0; h2 < 2; ++h2)
                redf[wnIdx * 128 + wm + mt * 16 + (lane >> 2) + h2 * 8] = smv[mt][h2];
    }
    __syncthreads();
    if (wnIdx == 0 && (lane & 3) == 0) {
        #pragma unroll
        for (int mt = 0; mt < 2; ++mt)
            #pragma unroll
            for (int h2 = 0; h2 < 2; ++h2) {
                const int row = wm + mt * 16 + (lane >> 2) + h2 * 8;
                const float tot = redf[row] + redf[128 + row] + redf[256 + row] + redf[384 + row];
                sumf[row] = 1.f / tot;
            }
    }
    __syncthreads();

    // ---- O = P @ V : warp tile 32x16 ----
    const int wm2 = (warp & 3) << 5;
    const int wn2 = (warp >> 2) << 4;   // 0,16,32,48

    float acc2[2][2][4];
    #pragma unroll
    for (int i = 0; i < 2; ++i)
        #pragma unroll
        for (int j = 0; j < 2; ++j)
            #pragma unroll
            for (int t = 0; t < 4; ++t) acc2[i][j][t] = 0.f;

    for (int kc = 0; kc < 8; ++kc) {
        #pragma unroll
        for (int ks = 0; ks < 2; ++ks) {
            uint32_t af[2][4];
            #pragma unroll
            for (int mt = 0; mt < 2; ++mt) {
                const int row = wm2 + mt * 16 + (lane & 15);
                const int qq  = (ks << 1) + (lane >> 4);
                LDSM_X4(af[mt][0], af[mt][1], af[mt][2], af[mt][3],
                        sb + AP + kc * 8192 + swz(row, qq));
            }
            const int rowb = wn2 + (lane & 7) + ((lane >> 4) << 3);
            const int qqb  = (ks << 1) + ((lane >> 3) & 1);
            uint32_t t0, t1, t2, t3;
            LDSM_X4(t0, t1, t2, t3, sb + AV + kc * 4096 + swz(rowb, qqb));
            uint32_t bf0[2] = { t0, t1 };
            uint32_t bf1[2] = { t2, t3 };
            #pragma unroll
            for (int mt = 0; mt < 2; ++mt) {
                MMA16816(acc2[mt][0], af[mt], bf0);
                MMA16816(acc2[mt][1], af[mt], bf1);
            }
        }
    }

    // ---- epilogue: scale by 1/rowsum, store fp16 ----
    #pragma unroll
    for (int mt = 0; mt < 2; ++mt) {
        const int rl0 = wm2 + mt * 16 + (lane >> 2);
        const float i0 = sumf[rl0];
        const float i1 = sumf[rl0 + 8];
        #pragma unroll
        for (int ntn = 0; ntn < 2; ++ntn) {
            const int col = wn2 + ntn * 8 + ((lane & 3) << 1);
            __half2 o0 = __float22half2_rn(make_float2(acc2[mt][ntn][0]*i0, acc2[mt][ntn][1]*i0));
            __half2 o1 = __float22half2_rn(make_float2(acc2[mt][ntn][2]*i1, acc2[mt][ntn][3]*i1));
            *(__half2*)(outh + (row0 + rl0) * DIM + h * HD + col) = o0;
            *(__half2*)(outh + (row0 + rl0 + 8) * DIM + h * HD + col) = o1;
        }
    }
}

// ---------------- launch ----------------
extern "C" void kernel_launch(void* const* d_in, const int* in_sizes, int n_in,
                              void* d_out, int out_size)
{
    const float* x     = (const float*)d_in[0];
    const float* ln1_g = (const float*)d_in[1];
    const float* ln1_b = (const float*)d_in[2];
    const float* ln2_g = (const float*)d_in[3];
    const float* ln2_b = (const float*)d_in[4];
    const float* wq    = (const float*)d_in[5];
    const float* wk    = (const float*)d_in[6];
    const float* wv    = (const float*)d_in[7];
    const float* wo    = (const float*)d_in[8];
    const float* bo    = (const float*)d_in[9];
    const float* relb  = (const float*)d_in[10];
    const float* wff1  = (const float*)d_in[11];
    const float* bff1  = (const float*)d_in[12];
    const float* wff2  = (const float*)d_in[13];
    const float* bff2  = (const float*)d_in[14];
    float* out = (float*)d_out;

    float *x1;
    __half *lnh, *ath, *hh, *wt, *qkvh, *vT;
    cudaGetSymbolAddress((void**)&x1,   g_x1);
    cudaGetSymbolAddress((void**)&lnh,  g_lnh);
    cudaGetSymbolAddress((void**)&ath,  g_ath);
    cudaGetSymbolAddress((void**)&hh,   g_hh);
    cudaGetSymbolAddress((void**)&wt,   g_wt);
    cudaGetSymbolAddress((void**)&qkvh, g_qkvh);
    cudaGetSymbolAddress((void**)&vT,   g_vT);

    __half* qh = qkvh;
    __half* kh = qkvh + (size_t)MROWS * DIM;
    __half* vh = qkvh + (size_t)2 * MROWS * DIM;

    cudaFuncSetAttribute(attn_mma, cudaFuncAttributeMaxDynamicSharedMemorySize, SMEM_ATTN2);
    cudaFuncSetAttribute((mma_gemm<4,1>), cudaFuncAttributeMaxDynamicSharedMemorySize, SMEM_MMAGEMM);
    cudaFuncSetAttribute((mma_gemm<2,0>), cudaFuncAttributeMaxDynamicSharedMemorySize, SMEM_MMAGEMM);
    cudaFuncSetAttribute((mma_gemm<3,0>), cudaFuncAttributeMaxDynamicSharedMemorySize, SMEM_MMAGEMM);

    const size_t OW = (size_t)1024 * 1024;
    __half *tq = wt;
    __half *to = wt + 3*OW;
    __half *t1 = wt + 4*OW;
    __half *t2 = wt + 8*OW;

    wsplit_kernel<0><<<dim3(32, 32),  256>>>(wq,   tq,        1024, 1024);
    wsplit_kernel<0><<<dim3(32, 32),  256>>>(wk,   wt + OW,   1024, 1024);
    wsplit_kernel<0><<<dim3(32, 32),  256>>>(wv,   wt + 2*OW, 1024, 1024);
    wsplit_kernel<0><<<dim3(32, 32),  256>>>(wo,   to,        1024, 1024);
    wsplit_kernel<1><<<dim3(128, 32), 256>>>(wff1, t1,        1024, 4096);
    wsplit_kernel<0><<<dim3(32, 64),  256>>>(wff2, t2,        2048, 1024);

    const dim3 gqkv(24, 128);
    const dim3 g1024(8, 128);
    const dim3 g4096(32, 128);

    ln_kernel<<<MROWS, 256>>>(x, ln1_g, ln1_b, lnh);
    mma_gemm<4,1><<<gqkv, 512, SMEM_MMAGEMM>>>(lnh, tq, nullptr,
        nullptr, nullptr, qkvh, MROWS, 1024, 1024);
    vtrans_kernel<<<dim3(DIM/32, MROWS/32), 256>>>(vh, vT);
    attn_mma<<<dim3(NW, HEADS, BATCH), 512, SMEM_ATTN2>>>(qh, kh, vT, relb, ath);
    mma_gemm<2,0><<<g1024, 512, SMEM_MMAGEMM>>>(ath, to, x1,
        bo, x, nullptr, MROWS, 1024, 1024);
    ln_kernel<<<MROWS, 256>>>(x1, ln2_g, ln2_b, lnh);
    mma_gemm<3,0><<<g4096, 512, SMEM_MMAGEMM>>>(lnh, t1, nullptr,
        bff1, nullptr, hh, MROWS, 4096, 1024);
    mma_gemm<2,0><<<g1024, 512, SMEM_MMAGEMM>>>(hh, t2, out,
        bff2, x1, nullptr, MROWS, 1024, 2048);
}

// round 8
// speedup vs baseline: 5.5408x; 1.0520x over previous
#include <cuda_runtime.h>
#include <cuda_bf16.h>
#include <cuda_fp16.h>
#include <math.h>
#include <stdint.h>

// ---------------- problem constants ----------------
#define BATCH 4
#define SEQ   4096
#define DIM   1024
#define HEADS 16
#define HD    64
#define WIN   128
#define NW    (SEQ / WIN)         // 32
#define MROWS (BATCH * SEQ)       // 16384
#define HIDDEN 2048               // = 2*DIM
#define FF1N  (2 * HIDDEN)        // 4096

// ---------------- scratch (device globals; allocation-free) ----------------
static __device__ __align__(128) float g_x1  [(size_t)MROWS * DIM];

static __device__ __align__(128) __half g_lnh [(size_t)MROWS * DIM];
static __device__ __align__(128) __half g_ath [(size_t)MROWS * DIM];
static __device__ __align__(128) __half g_hh  [(size_t)MROWS * HIDDEN];
static __device__ __align__(128) __half g_qkvh[(size_t)3 * MROWS * DIM];
static __device__ __align__(128) __half g_vT  [(size_t)DIM * MROWS];

// transposed fp16 weights [N][K] K-major
#define WT_TOTAL (10u * 1024u * 1024u)
static __device__ __align__(128) __half g_wt[WT_TOTAL];

// ================= helpers =================
__device__ __forceinline__ uint32_t smem_u32(const void* p) {
    uint32_t a;
    asm("{ .reg .u64 t; cvta.to.shared.u64 t, %1; cvt.u32.u64 %0, t; }" : "=r"(a) : "l"(p));
    return a;
}

#define CP_ASYNC16(dst, src) \
    asm volatile("cp.async.cg.shared.global [%0], [%1], 16;" :: "r"(dst), "l"(src))
#define CP_COMMIT() asm volatile("cp.async.commit_group;" ::: "memory")
#define CP_WAIT2()  asm volatile("cp.async.wait_group 2;" ::: "memory")
#define CP_WAIT0()  asm volatile("cp.async.wait_group 0;" ::: "memory")

#define LDSM_X4(r0, r1, r2, r3, addr) \
    asm volatile("ldmatrix.sync.aligned.m8n8.x4.shared.b16 {%0,%1,%2,%3}, [%4];" \
        : "=r"(r0), "=r"(r1), "=r"(r2), "=r"(r3) : "r"(addr))

#define MMA16816(d, a, b) \
    asm volatile("mma.sync.aligned.m16n8k16.row.col.f32.f16.f16.f32 " \
        "{%0,%1,%2,%3}, {%4,%5,%6,%7}, {%8,%9}, {%0,%1,%2,%3};" \
        : "+f"((d)[0]), "+f"((d)[1]), "+f"((d)[2]), "+f"((d)[3]) \
        : "r"((a)[0]), "r"((a)[1]), "r"((a)[2]), "r"((a)[3]), "r"((b)[0]), "r"((b)[1]))

// smem tile: rows x 32 fp16 (64B/row), XOR swizzle on 16B quarters
__device__ __forceinline__ uint32_t swz(int r, int q) {
    return (uint32_t)(r * 64 + ((q ^ ((r >> 1) & 3)) << 4));
}

__device__ __forceinline__ uint2 pack4h(float4 v) {
    __half2 h01 = __float22half2_rn(make_float2(v.x, v.y));
    __half2 h23 = __float22half2_rn(make_float2(v.z, v.w));
    uint2 r;
    r.x = *reinterpret_cast<uint32_t*>(&h01);
    r.y = *reinterpret_cast<uint32_t*>(&h23);
    return r;
}

__device__ __forceinline__ float gelu_exact(float x) {
    return 0.5f * x * (1.f + erff(x * 0.70710678118654752f));
}

// ---------------- LayerNorm -> fp16 ----------------
__global__ void __launch_bounds__(256) ln_kernel(const float* __restrict__ x,
                                                 const float* __restrict__ g,
                                                 const float* __restrict__ b,
                                                 __half* __restrict__ oh)
{
    const int row = blockIdx.x;
    const int tid = threadIdx.x;
    const float4 v = ((const float4*)(x + (size_t)row * DIM))[tid];
    float s  = v.x + v.y + v.z + v.w;
    float ss = v.x*v.x + v.y*v.y + v.z*v.z + v.w*v.w;
    #pragma unroll
    for (int o = 16; o; o >>= 1) {
        s  += __shfl_xor_sync(0xffffffffu, s,  o);
        ss += __shfl_xor_sync(0xffffffffu, ss, o);
    }
    __shared__ float s1[8], s2[8];
    const int w = tid >> 5, l = tid & 31;
    if (l == 0) { s1[w] = s; s2[w] = ss; }
    __syncthreads();
    if (w == 0) {
        s  = (l < 8) ? s1[l] : 0.f;
        ss = (l < 8) ? s2[l] : 0.f;
        #pragma unroll
        for (int o = 4; o; o >>= 1) {
            s  += __shfl_xor_sync(0xffffffffu, s,  o);
            ss += __shfl_xor_sync(0xffffffffu, ss, o);
        }
        if (l == 0) { s1[0] = s * (1.f / DIM); s2[0] = ss * (1.f / DIM); }
    }
    __syncthreads();
    const float m   = s1[0];
    const float var = s2[0] - m * m;
    const float r   = rsqrtf(var + 1e-5f);
    const float4 gv = ((const float4*)g)[tid];
    const float4 bv = ((const float4*)b)[tid];
    float4 o;
    o.x = (v.x - m) * r * gv.x + bv.x;
    o.y = (v.y - m) * r * gv.y + bv.y;
    o.z = (v.z - m) * r * gv.z + bv.z;
    o.w = (v.w - m) * r * gv.w + bv.w;
    ((uint2*)(oh + (size_t)row * DIM))[tid] = pack4h(o);
}

// ---------------- weight transpose: W[K][N] fp32 -> T[N][K] fp16 -----------
template<int PERM>
__global__ void __launch_bounds__(256) wsplit_kernel(const float* __restrict__ W,
    __half* __restrict__ Th, int K, int N)
{
    __shared__ float t[32][33];
    const int n0 = blockIdx.x * 32, k0 = blockIdx.y * 32;
    const int tx = threadIdx.x & 31, ty = threadIdx.x >> 5;
    int sc = n0 + tx;
    if (PERM) sc = (sc & 1) ? (sc >> 1) + HIDDEN : (sc >> 1);
    #pragma unroll
    for (int j = 0; j < 4; ++j)
        t[ty + 8*j][tx] = W[(size_t)(k0 + ty + 8*j) * N + sc];
    __syncthreads();
    #pragma unroll
    for (int j = 0; j < 4; ++j) {
        const float v = t[tx][ty + 8*j];
        Th[(size_t)(n0 + ty + 8*j) * K + k0 + tx] = __float2half_rn(v);
    }
}

// ---------------- fp16 transpose: V[MROWS][DIM] -> vT[DIM][MROWS] ----------
__global__ void __launch_bounds__(256) vtrans_kernel(const __half* __restrict__ V,
                                                     __half* __restrict__ vT)
{
    __shared__ __half t[32][33];
    const int c0 = blockIdx.x * 32, r0 = blockIdx.y * 32;
    const int tx = threadIdx.x & 31, ty = threadIdx.x >> 5;
    #pragma unroll
    for (int j = 0; j < 4; ++j)
        t[ty + 8*j][tx] = V[(size_t)(r0 + ty + 8*j) * DIM + c0 + tx];
    __syncthreads();
    #pragma unroll
    for (int j = 0; j < 4; ++j)
        vT[(size_t)(c0 + ty + 8*j) * MROWS + r0 + tx] = t[tx][ty + 8*j];
}

// ---------------- HMMA GEMM: C[M,N] = A*B, fp16 ----------------------------
// Block 128x256, 8 warps (2m x 4n grid of 64x64 warp tiles), BK=32,
// 4-stage cp.async (wait 2).
// EPI: 0 C=AB | 2 C=AB+bias+res | 3 fused geglu -> fp16 | 4 fp16 out (+q scale)
// QKV: if 1, output column-blocks route to q/k/v slabs (each M x 1024).
#define STAGE_BYTES 24576
#define OFF_A  0
#define OFF_B  8192
#define SMEM_MMAGEMM (4 * STAGE_BYTES)   // 98304

template<int EPI, int QKV>
__global__ void __launch_bounds__(256, 1) mma_gemm(
    const __half* __restrict__ A, const __half* __restrict__ B,
    float* __restrict__ C, const float* __restrict__ bias,
    const float* __restrict__ res, __half* __restrict__ Oh,
    int M, int N, int K)
{
    extern __shared__ char smem_raw[];
    const uint32_t sb = smem_u32(smem_raw);
    const int tid = threadIdx.x, lane = tid & 31, warp = tid >> 5;
    const int bxw = blockIdx.x, by = blockIdx.y;
    const int wm = (warp & 1) << 6;   // 0,64
    const int wn = (warp >> 1) << 6;  // 0,64,128,192

    int bx = bxw;
    if (QKV) {
        if (EPI == 4) Oh += (size_t)(bxw >> 2) * M * N;
        else          C  += (size_t)(bxw >> 2) * M * N;
        bx = bxw & 3;
    }

    const __half* Ag = A + (size_t)(by * 128) * K;
    const __half* Bg = B + (size_t)(bxw * 256) * K;

    const int CHUNKS = K >> 5;
    const int rl = tid >> 2, ql = tid & 3;

    #define LOAD_CHUNK(c, s) do { \
        const uint32_t st_ = sb + (s) * STAGE_BYTES; \
        const int kc_ = (c) << 5; \
        { const uint32_t o_ = swz(rl, ql); \
          CP_ASYNC16(st_ + OFF_A + o_, Ag + (size_t)rl * K + kc_ + ql * 8); \
          CP_ASYNC16(st_ + OFF_A + swz(rl + 64, ql), Ag + (size_t)(rl + 64) * K + kc_ + ql * 8); } \
        _Pragma("unroll") \
        for (int i_ = 0; i_ < 4; ++i_) { \
            const int r_ = rl + 64 * i_; \
            CP_ASYNC16(st_ + OFF_B + swz(r_, ql), Bg + (size_t)r_ * K + kc_ + ql * 8); \
        } \
    } while (0)

    float acc[4][8][4];
    #pragma unroll
    for (int i = 0; i < 4; ++i)
        #pragma unroll
        for (int j = 0; j < 8; ++j)
            #pragma unroll
            for (int t = 0; t < 4; ++t) acc[i][j][t] = 0.f;

    LOAD_CHUNK(0, 0); CP_COMMIT();
    LOAD_CHUNK(1, 1); CP_COMMIT();
    LOAD_CHUNK(2, 2); CP_COMMIT();

    for (int c = 0; c < CHUNKS; ++c) {
        CP_WAIT2();
        __syncthreads();
        if (c + 3 < CHUNKS) LOAD_CHUNK(c + 3, (c + 3) & 3);
        CP_COMMIT();

        const uint32_t st = sb + (c & 3) * STAGE_BYTES;
        #pragma unroll
        for (int ks = 0; ks < 2; ++ks) {
            uint32_t af[4][4];
            #pragma unroll
            for (int mt = 0; mt < 4; ++mt) {
                const int row = wm + mt * 16 + (lane & 15);
                const int q   = (ks << 1) + (lane >> 4);
                LDSM_X4(af[mt][0], af[mt][1], af[mt][2], af[mt][3],
                        st + OFF_A + swz(row, q));
            }
            uint32_t bf[8][2];
            #pragma unroll
            for (int np = 0; np < 4; ++np) {
                const int row = wn + np * 16 + (lane & 7) + ((lane >> 4) << 3);
                const int q   = (ks << 1) + ((lane >> 3) & 1);
                uint32_t t0, t1, t2, t3;
                LDSM_X4(t0, t1, t2, t3, st + OFF_B + swz(row, q));
                bf[2*np][0] = t0;   bf[2*np][1] = t1;
                bf[2*np+1][0] = t2; bf[2*np+1][1] = t3;
            }
            #pragma unroll
            for (int mt = 0; mt < 4; ++mt)
                #pragma unroll
                for (int nt = 0; nt < 8; ++nt)
                    MMA16816(acc[mt][nt], af[mt], bf[nt]);
        }
    }

    if (EPI == 3) {
        #pragma unroll
        for (int mt = 0; mt < 4; ++mt) {
            const int gr = by * 128 + wm + mt * 16 + (lane >> 2);
            #pragma unroll
            for (int nt = 0; nt < 8; ++nt) {
                const int col = bx * 256 + wn + nt * 8 + ((lane & 3) << 1);
                const int j = col >> 1;
                const float bv = bias[j];
                const float bg = bias[j + HIDDEN];
                const float h0 = (acc[mt][nt][0] + bv) * gelu_exact(acc[mt][nt][1] + bg);
                const float h1 = (acc[mt][nt][2] + bv) * gelu_exact(acc[mt][nt][3] + bg);
                Oh[(size_t)gr * HIDDEN + j]       = __float2half_rn(h0);
                Oh[(size_t)(gr + 8) * HIDDEN + j] = __float2half_rn(h1);
            }
        }
    } else if (EPI == 4) {
        const float sc = (QKV && (bxw >> 2) == 0) ? 0.125f : 1.0f;
        #pragma unroll
        for (int mt = 0; mt < 4; ++mt) {
            const int gr = by * 128 + wm + mt * 16 + (lane >> 2);
            #pragma unroll
            for (int nt = 0; nt < 8; ++nt) {
                const int col = bx * 256 + wn + nt * 8 + ((lane & 3) << 1);
                __half2 o0 = __float22half2_rn(make_float2(acc[mt][nt][0]*sc, acc[mt][nt][1]*sc));
                __half2 o1 = __float22half2_rn(make_float2(acc[mt][nt][2]*sc, acc[mt][nt][3]*sc));
                *(__half2*)(Oh + (size_t)gr * N + col) = o0;
                *(__half2*)(Oh + (size_t)(gr + 8) * N + col) = o1;
            }
        }
    } else {
        #pragma unroll
        for (int mt = 0; mt < 4; ++mt) {
            const int gr = by * 128 + wm + mt * 16 + (lane >> 2);
            #pragma unroll
            for (int nt = 0; nt < 8; ++nt) {
                const int col = bx * 256 + wn + nt * 8 + ((lane & 3) << 1);
                float2 v0 = make_float2(acc[mt][nt][0], acc[mt][nt][1]);
                float2 v1 = make_float2(acc[mt][nt][2], acc[mt][nt][3]);
                if (EPI >= 1) {
                    const float2 bb = *(const float2*)(bias + col);
                    v0.x += bb.x; v0.y += bb.y; v1.x += bb.x; v1.y += bb.y;
                }
                if (EPI == 2) {
                    const float2 r0v = *(const float2*)(res + (size_t)gr * N + col);
                    const float2 r1v = *(const float2*)(res + (size_t)(gr + 8) * N + col);
                    v0.x += r0v.x; v0.y += r0v.y; v1.x += r1v.x; v1.y += r1v.y;
                }
                *(float2*)(C + (size_t)gr * N + col) = v0;
                *(float2*)(C + (size_t)(gr + 8) * N + col) = v1;
            }
        }
    }
    #undef LOAD_CHUNK
}

// ---------------- HMMA sliding-window attention -----------------------------
#define AQ 0
#define AK 16384
#define AV 49152
#define AP 81920
#define ABIAS 147456
#define ARED  148480
#define ASUM  150528
#define SMEM_ATTN2 151040

__global__ void __launch_bounds__(512, 1) attn_mma(
    const __half* __restrict__ q, const __half* __restrict__ k,
    const __half* __restrict__ vT, const float* __restrict__ rel_bias,
    __half* __restrict__ outh)
{
    extern __shared__ char smc[];
    const uint32_t sb = smem_u32(smc);
    const int n = blockIdx.x, h = blockIdx.y, b = blockIdx.z;
    const int tid = threadIdx.x, lane = tid & 31, warp = tid >> 5;
    const size_t row0 = (size_t)b * SEQ + (size_t)n * WIN;

    float* bsf  = (float*)(smc + ABIAS);
    float* redf = (float*)(smc + ARED);
    float* sumf = (float*)(smc + ASUM);

    #pragma unroll
    for (int i = 0; i < 2; ++i) {
        const int row = tid >> 2, Q4 = (tid & 3) + 4 * i;
        const uint32_t off = AQ + (Q4 >> 2) * 8192 + swz(row, Q4 & 3);
        CP_ASYNC16(sb + off, q + (row0 + row) * DIM + h * HD + Q4 * 8);
    }
    #pragma unroll
    for (int i = 0; i < 4; ++i) {
        const int row = (tid >> 2) + 128 * (i >> 1);
        const int Q4 = (tid & 3) + 4 * (i & 1);
        const uint32_t off = AK + (Q4 >> 2) * 16384 + swz(row, Q4 & 3);
        if (n == 0 && row < 128)
            *(uint4*)(smc + off) = make_uint4(0, 0, 0, 0);
        else
            CP_ASYNC16(sb + off, k + (row0 - WIN + row) * DIM + h * HD + Q4 * 8);
    }
    #pragma unroll
    for (int i = 0; i < 4; ++i) {
        const int d = tid >> 3, J4 = (tid & 7) + 8 * i;
        const uint32_t off = AV + (J4 >> 2) * 4096 + swz(d, J4 & 3);
        if (n == 0 && J4 < 16)
            *(uint4*)(smc + off) = make_uint4(0, 0, 0, 0);
        else
            CP_ASYNC16(sb + off, vT + (size_t)(h * HD + d) * MROWS + row0 - WIN + J4 * 8);
    }
    if (tid < 256) bsf[tid] = rel_bias[h * 256 + tid];
    CP_COMMIT();
    CP_WAIT0();
    __syncthreads();

    const int wm  = (warp & 3) << 5;
    const int wnS = (warp >> 2) << 6;
    const int wnIdx = warp >> 2;

    float acc[2][8][4];
    #pragma unroll
    for (int i = 0; i < 2; ++i)
        #pragma unroll
        for (int j = 0; j < 8; ++j)
            #pragma unroll
            for (int t = 0; t < 4; ++t) acc[i][j][t] = 0.f;

    #pragma unroll
    for (int kc = 0; kc < 2; ++kc)
        #pragma unroll
        for (int ks = 0; ks < 2; ++ks) {
            uint32_t af[2][4];
            #pragma unroll
            for (int mt = 0; mt < 2; ++mt) {
                const int row = wm + mt * 16 + (lane & 15);
                const int qq  = (ks << 1) + (lane >> 4);
                LDSM_X4(af[mt][0], af[mt][1], af[mt][2], af[mt][3],
                        sb + AQ + kc * 8192 + swz(row, qq));
            }
            uint32_t bf[8][2];
            #pragma unroll
            for (int np = 0; np < 4; ++np) {
                const int row = wnS + np * 16 + (lane & 7) + ((lane >> 4) << 3);
                const int qq  = (ks << 1) + ((lane >> 3) & 1);
                uint32_t t0, t1, t2, t3;
                LDSM_X4(t0, t1, t2, t3, sb + AK + kc * 16384 + swz(row, qq));
                bf[2*np][0] = t0;   bf[2*np][1] = t1;
                bf[2*np+1][0] = t2; bf[2*np+1][1] = t3;
            }
            #pragma unroll
            for (int mt = 0; mt < 2; ++mt)
                #pragma unroll
                for (int nt = 0; nt < 8; ++nt)
                    MMA16816(acc[mt][nt], af[mt], bf[nt]);
        }

    float mxv[2][2];
    #pragma unroll
    for (int mt = 0; mt < 2; ++mt)
        #pragma unroll
        for (int h2 = 0; h2 < 2; ++h2) {
            const int row = wm + mt * 16 + (lane >> 2) + h2 * 8;
            float m = -1e30f;
            #pragma unroll
            for (int nt = 0; nt < 8; ++nt) {
                const int c0 = wnS + nt * 8;
                const bool dead = (c0 > wm + mt * 16 + 143) ||
                                  (n == 0 && c0 + 8 <= 128);
                if (dead) {
                    acc[mt][nt][h2*2+0] = -1e30f;
                    acc[mt][nt][h2*2+1] = -1e30f;
                    continue;
                }
                #pragma unroll
                for (int cc = 0; cc < 2; ++cc) {
                    const int col = c0 + ((lane & 3) << 1) + cc;
                    const int e = h2 * 2 + cc;
                    const int dist = row + WIN - col;
                    const bool valid = (dist >= 0) && (n > 0 || col >= WIN);
                    const float s = valid ? (acc[mt][nt][e] + bsf[dist]) : -1e30f;
                    acc[mt][nt][e] = s;
                    m = fmaxf(m, s);
                }
            }
            mxv[mt][h2] = m;
        }
    #pragma unroll
    for (int mt = 0; mt < 2; ++mt)
        #pragma unroll
        for (int h2 = 0; h2 < 2; ++h2) {
            mxv[mt][h2] = fmaxf(mxv[mt][h2], __shfl_xor_sync(0xffffffffu, mxv[mt][h2], 1));
            mxv[mt][h2] = fmaxf(mxv[mt][h2], __shfl_xor_sync(0xffffffffu, mxv[mt][h2], 2));
        }
    if ((lane & 3) == 0) {
        #pragma unroll
        for (int mt = 0; mt < 2; ++mt)
            #pragma unroll
            for (int h2 = 0; h2 < 2; ++h2)
                redf[wnIdx * 128 + wm + mt * 16 + (lane >> 2) + h2 * 8] = mxv[mt][h2];
    }
    __syncthreads();
    #pragma unroll
    for (int mt = 0; mt < 2; ++mt)
        #pragma unroll
        for (int h2 = 0; h2 < 2; ++h2) {
            const int row = wm + mt * 16 + (lane >> 2) + h2 * 8;
            float m = redf[row];
            m = fmaxf(m, redf[128 + row]);
            m = fmaxf(m, redf[256 + row]);
            m = fmaxf(m, redf[384 + row]);
            mxv[mt][h2] = m;
        }
    __syncthreads();

    float smv[2][2];
    #pragma unroll
    for (int mt = 0; mt < 2; ++mt)
        #pragma unroll
        for (int h2 = 0; h2 < 2; ++h2) {
            const int row = wm + mt * 16 + (lane >> 2) + h2 * 8;
            const float m = mxv[mt][h2];
            float rs = 0.f;
            #pragma unroll
            for (int nt = 0; nt < 8; ++nt) {
                const int c0 = wnS + nt * 8;
                const int col = c0 + ((lane & 3) << 1);
                const int c5 = col & 31;
                const uint32_t off = AP + (col >> 5) * 8192 + row * 64 +
                    ((((c5 >> 3)) ^ ((row >> 1) & 3)) << 4) + (c5 & 7) * 2;
                const bool dead = (c0 > wm + mt * 16 + 143) ||
                                  (n == 0 && c0 + 8 <= 128);
                if (dead) {
                    *(__half2*)(smc + off) = __float2half2_rn(0.f);
                } else {
                    const float p0 = __expf(acc[mt][nt][h2*2+0] - m);
                    const float p1 = __expf(acc[mt][nt][h2*2+1] - m);
                    rs += p0 + p1;
                    *(__half2*)(smc + off) = __float22half2_rn(make_float2(p0, p1));
                }
            }
            smv[mt][h2] = rs;
        }
    #pragma unroll
    for (int mt = 0; mt < 2; ++mt)
        #pragma unroll
        for (int h2 = 0; h2 < 2; ++h2) {
            smv[mt][h2] += __shfl_xor_sync(0xffffffffu, smv[mt][h2], 1);
            smv[mt][h2] += __shfl_xor_sync(0xffffffffu, smv[mt][h2], 2);
        }
    if ((lane & 3) == 0) {
        #pragma unroll
        for (int mt = 0; mt < 2; ++mt)
            #pragma unroll
            for (int h2 = 0; h2 < 2; ++h2)
                redf[wnIdx * 128 + wm + mt * 16 + (lane >> 2) + h2 * 8] = smv[mt][h2];
    }
    __syncthreads();
    if (wnIdx == 0 && (lane & 3) == 0) {
        #pragma unroll
        for (int mt = 0; mt < 2; ++mt)
            #pragma unroll
            for (int h2 = 0; h2 < 2; ++h2) {
                const int row = wm + mt * 16 + (lane >> 2) + h2 * 8;
                const float tot = redf[row] + redf[128 + row] + redf[256 + row] + redf[384 + row];
                sumf[row] = 1.f / tot;
            }
    }
    __syncthreads();

    const int wm2 = (warp & 3) << 5;
    const int wn2 = (warp >> 2) << 4;

    float acc2[2][2][4];
    #pragma unroll
    for (int i = 0; i < 2; ++i)
        #pragma unroll
        for (int j = 0; j < 2; ++j)
            #pragma unroll
            for (int t = 0; t < 4; ++t) acc2[i][j][t] = 0.f;

    for (int kc = 0; kc < 8; ++kc) {
        #pragma unroll
        for (int ks = 0; ks < 2; ++ks) {
            uint32_t af[2][4];
            #pragma unroll
            for (int mt = 0; mt < 2; ++mt) {
                const int row = wm2 + mt * 16 + (lane & 15);
                const int qq  = (ks << 1) + (lane >> 4);
                LDSM_X4(af[mt][0], af[mt][1], af[mt][2], af[mt][3],
                        sb + AP + kc * 8192 + swz(row, qq));
            }
            const int rowb = wn2 + (lane & 7) + ((lane >> 4) << 3);
            const int qqb  = (ks << 1) + ((lane >> 3) & 1);
            uint32_t t0, t1, t2, t3;
            LDSM_X4(t0, t1, t2, t3, sb + AV + kc * 4096 + swz(rowb, qqb));
            uint32_t bf0[2] = { t0, t1 };
            uint32_t bf1[2] = { t2, t3 };
            #pragma unroll
            for (int mt = 0; mt < 2; ++mt) {
                MMA16816(acc2[mt][0], af[mt], bf0);
                MMA16816(acc2[mt][1], af[mt], bf1);
            }
        }
    }

    #pragma unroll
    for (int mt = 0; mt < 2; ++mt) {
        const int rl0 = wm2 + mt * 16 + (lane >> 2);
        const float i0 = sumf[rl0];
        const float i1 = sumf[rl0 + 8];
        #pragma unroll
        for (int ntn = 0; ntn < 2; ++ntn) {
            const int col = wn2 + ntn * 8 + ((lane & 3) << 1);
            __half2 o0 = __float22half2_rn(make_float2(acc2[mt][ntn][0]*i0, acc2[mt][ntn][1]*i0));
            __half2 o1 = __float22half2_rn(make_float2(acc2[mt][ntn][2]*i1, acc2[mt][ntn][3]*i1));
            *(__half2*)(outh + (row0 + rl0) * DIM + h * HD + col) = o0;
            *(__half2*)(outh + (row0 + rl0 + 8) * DIM + h * HD + col) = o1;
        }
    }
}

// ---------------- launch ----------------
extern "C" void kernel_launch(void* const* d_in, const int* in_sizes, int n_in,
                              void* d_out, int out_size)
{
    const float* x     = (const float*)d_in[0];
    const float* ln1_g = (const float*)d_in[1];
    const float* ln1_b = (const float*)d_in[2];
    const float* ln2_g = (const float*)d_in[3];
    const float* ln2_b = (const float*)d_in[4];
    const float* wq    = (const float*)d_in[5];
    const float* wk    = (const float*)d_in[6];
    const float* wv    = (const float*)d_in[7];
    const float* wo    = (const float*)d_in[8];
    const float* bo    = (const float*)d_in[9];
    const float* relb  = (const float*)d_in[10];
    const float* wff1  = (const float*)d_in[11];
    const float* bff1  = (const float*)d_in[12];
    const float* wff2  = (const float*)d_in[13];
    const float* bff2  = (const float*)d_in[14];
    float* out = (float*)d_out;

    float *x1;
    __half *lnh, *ath, *hh, *wt, *qkvh, *vT;
    cudaGetSymbolAddress((void**)&x1,   g_x1);
    cudaGetSymbolAddress((void**)&lnh,  g_lnh);
    cudaGetSymbolAddress((void**)&ath,  g_ath);
    cudaGetSymbolAddress((void**)&hh,   g_hh);
    cudaGetSymbolAddress((void**)&wt,   g_wt);
    cudaGetSymbolAddress((void**)&qkvh, g_qkvh);
    cudaGetSymbolAddress((void**)&vT,   g_vT);

    __half* qh = qkvh;
    __half* kh = qkvh + (size_t)MROWS * DIM;
    __half* vh = qkvh + (size_t)2 * MROWS * DIM;

    cudaFuncSetAttribute(attn_mma, cudaFuncAttributeMaxDynamicSharedMemorySize, SMEM_ATTN2);
    cudaFuncSetAttribute((mma_gemm<4,1>), cudaFuncAttributeMaxDynamicSharedMemorySize, SMEM_MMAGEMM);
    cudaFuncSetAttribute((mma_gemm<2,0>), cudaFuncAttributeMaxDynamicSharedMemorySize, SMEM_MMAGEMM);
    cudaFuncSetAttribute((mma_gemm<3,0>), cudaFuncAttributeMaxDynamicSharedMemorySize, SMEM_MMAGEMM);

    const size_t OW = (size_t)1024 * 1024;
    __half *tq = wt;
    __half *to = wt + 3*OW;
    __half *t1 = wt + 4*OW;
    __half *t2 = wt + 8*OW;

    wsplit_kernel<0><<<dim3(32, 32),  256>>>(wq,   tq,        1024, 1024);
    wsplit_kernel<0><<<dim3(32, 32),  256>>>(wk,   wt + OW,   1024, 1024);
    wsplit_kernel<0><<<dim3(32, 32),  256>>>(wv,   wt + 2*OW, 1024, 1024);
    wsplit_kernel<0><<<dim3(32, 32),  256>>>(wo,   to,        1024, 1024);
    wsplit_kernel<1><<<dim3(128, 32), 256>>>(wff1, t1,        1024, 4096);
    wsplit_kernel<0><<<dim3(32, 64),  256>>>(wff2, t2,        2048, 1024);

    const dim3 gqkv(12, 128);   // 3 slabs x 4 col-blocks of 256
    const dim3 g1024(4, 128);
    const dim3 g4096(16, 128);

    ln_kernel<<<MROWS, 256>>>(x, ln1_g, ln1_b, lnh);
    mma_gemm<4,1><<<gqkv, 256, SMEM_MMAGEMM>>>(lnh, tq, nullptr,
        nullptr, nullptr, qkvh, MROWS, 1024, 1024);
    vtrans_kernel<<<dim3(DIM/32, MROWS/32), 256>>>(vh, vT);
    attn_mma<<<dim3(NW, HEADS, BATCH), 512, SMEM_ATTN2>>>(qh, kh, vT, relb, ath);
    mma_gemm<2,0><<<g1024, 256, SMEM_MMAGEMM>>>(ath, to, x1,
        bo, x, nullptr, MROWS, 1024, 1024);
    ln_kernel<<<MROWS, 256>>>(x1, ln2_g, ln2_b, lnh);
    mma_gemm<3,0><<<g4096, 256, SMEM_MMAGEMM>>>(lnh, t1, nullptr,
        bff1, nullptr, hh, MROWS, 4096, 1024);
    mma_gemm<2,0><<<g1024, 256, SMEM_MMAGEMM>>>(hh, t2, out,
        bff2, x1, nullptr, MROWS, 1024, 2048);
}